// round 10
// baseline (speedup 1.0000x reference)
#include <cuda_runtime.h>
#include <cuda_bf16.h>
#include <math.h>
#include <stdint.h>

#define SEQ    2048
#define DM     2048
#define NH     16
#define HD     128
#define NB     2
#define MTOT   (NB * SEQ)          // 4096
#define K3     4096                // split width: [hi(2048) | lo(2048)]
#define SAW    72                  // gemm2 smem row stride (144B)
#define SF     136                 // flash smem row stride in bf16 (272B)

// gemm2 smem layout (dynamic)
#define A_STAGE (256 * SAW * 2)    // 36864 B
#define B_STAGE (128 * SAW * 2)    // 18432 B
#define B_OFF   (3 * A_STAGE)
#define GEMM2_SMEM (3 * A_STAGE + 3 * B_STAGE)   // 165888 B

// flash smem layout (dynamic): Q hi/lo resident + 2 KV stages
#define F_ROWB   (SF * 2)                 // 272 B per row
#define F_QHI    0
#define F_QLO    (128 * F_ROWB)           // 34816
#define F_KV0    (2 * 128 * F_ROWB)       // 69632
#define F_OKHI   0
#define F_OKLO   (64 * F_ROWB)
#define F_OVHI   (2 * 64 * F_ROWB)
#define F_OVLO   (3 * 64 * F_ROWB)
#define F_STG    (4 * 64 * F_ROWB)        // 69632
#define FLASH_SMEM (F_KV0 + 2 * F_STG)    // 208896 B

// ---------------- scratch (device globals: allocation-free rule) ------------
static __device__ float g_cos[SEQ * (HD / 2)];
static __device__ float g_sin[SEQ * (HD / 2)];
static __device__ __nv_bfloat16 g_xs [(size_t)MTOT * K3];   // x split (K3 layout)
static __device__ __nv_bfloat16 g_ws [4ULL * DM * K3];      // W splits (K3 layout)
static __device__ __nv_bfloat16 g_aos[(size_t)MTOT * K3];   // attn-out split (K3)
static __device__ __nv_bfloat16 g_qhi[(size_t)MTOT * DM];
static __device__ __nv_bfloat16 g_qlo[(size_t)MTOT * DM];
static __device__ __nv_bfloat16 g_khi[(size_t)MTOT * DM];
static __device__ __nv_bfloat16 g_klo[(size_t)MTOT * DM];
static __device__ __nv_bfloat16 g_vhi[(size_t)MTOT * DM];
static __device__ __nv_bfloat16 g_vlo[(size_t)MTOT * DM];

// ---------------- PTX helpers (baseline ISA only) ---------------------------
__device__ __forceinline__ uint32_t smem_u32(const void* p) {
    uint32_t a;
    asm("{ .reg .u64 t; cvta.to.shared.u64 t, %1; cvt.u32.u64 %0, t; }"
        : "=r"(a) : "l"(p));
    return a;
}

__device__ __forceinline__ void cp16(uint32_t saddr, const void* g) {
    asm volatile("cp.async.cg.shared.global [%0], [%1], 16;"
                 :: "r"(saddr), "l"(g));
}

__device__ __forceinline__ void ldm_x4(uint32_t addr, uint32_t& r0, uint32_t& r1,
                                       uint32_t& r2, uint32_t& r3) {
    asm volatile("ldmatrix.sync.aligned.m8n8.x4.shared.b16 {%0,%1,%2,%3}, [%4];"
                 : "=r"(r0), "=r"(r1), "=r"(r2), "=r"(r3) : "r"(addr));
}

__device__ __forceinline__ void ldm_x4t(uint32_t addr, uint32_t& r0, uint32_t& r1,
                                        uint32_t& r2, uint32_t& r3) {
    asm volatile("ldmatrix.sync.aligned.m8n8.x4.trans.shared.b16 {%0,%1,%2,%3}, [%4];"
                 : "=r"(r0), "=r"(r1), "=r"(r2), "=r"(r3) : "r"(addr));
}

__device__ __forceinline__ void mma_bf16(float* c, const uint32_t* a, const uint32_t* b) {
    asm volatile(
        "mma.sync.aligned.m16n8k16.row.col.f32.bf16.bf16.f32 "
        "{%0,%1,%2,%3}, {%4,%5,%6,%7}, {%8,%9}, {%0,%1,%2,%3};"
        : "+f"(c[0]), "+f"(c[1]), "+f"(c[2]), "+f"(c[3])
        : "r"(a[0]), "r"(a[1]), "r"(a[2]), "r"(a[3]), "r"(b[0]), "r"(b[1]));
}

__device__ __forceinline__ uint32_t pack_bf16x2(float a, float b) {
    __nv_bfloat162 h = __floats2bfloat162_rn(a, b);
    return *(uint32_t*)&h;
}

// ---------------- RoPE table (match jnp: fp32 angle, accurate trig) ---------
__global__ void rope_table_kernel()
{
    int s = blockIdx.x;
    int i = threadIdx.x;
    double e    = ((double)(2 * i)) / (double)HD;
    double powd = pow(10000.0, e);
    float  invf = (float)(1.0 / powd);
    float  fr   = (float)s * invf;
    double a    = (double)fr;
    g_cos[s * (HD / 2) + i] = (float)cos(a);
    g_sin[s * (HD / 2) + i] = (float)sin(a);
}

// ---------------- bf16 hi/lo split of x into K3-interleaved layout ----------
__global__ __launch_bounds__(256) void split_x_kernel(const float* __restrict__ src)
{
    int i = blockIdx.x * 256 + threadIdx.x;
    size_t r  = (size_t)(i >> 11);
    int    cc = i & 2047;
    float v = src[i];
    __nv_bfloat16 hi = __float2bfloat16(v);
    float hv = __bfloat162float(hi);
    __nv_bfloat16 lo = __float2bfloat16(v - hv);
    g_xs[r * K3 + cc]        = hi;
    g_xs[r * K3 + 2048 + cc] = lo;
}

// ---------------- split all 4 weight matrices in one launch -----------------
__global__ __launch_bounds__(256) void split_w_kernel(
    const float* __restrict__ W0, const float* __restrict__ W1,
    const float* __restrict__ W2, const float* __restrict__ W3)
{
    int i = blockIdx.x * 256 + threadIdx.x;      // 0 .. 4*4M-1
    int w = i >> 22;
    int j = i & ((1 << 22) - 1);
    const float* src = (w == 0) ? W0 : (w == 1) ? W1 : (w == 2) ? W2 : W3;
    float v = src[j];
    size_t r  = (size_t)(j >> 11);
    int    cc = j & 2047;
    __nv_bfloat16 hi = __float2bfloat16(v);
    float hv = __bfloat162float(hi);
    __nv_bfloat16 lo = __float2bfloat16(v - hv);
    __nv_bfloat16* dst = g_ws + (size_t)w * DM * K3;
    dst[r * K3 + cc]        = hi;
    dst[r * K3 + 2048 + cc] = lo;
}

// ---------------- bf16x3 GEMM: 256x128 CTA tile, 64x64 warp tile ------------
// vmode=1 (QKV): z=0 -> RoPE+split into g_qhi/qlo ; z=1 -> RoPE+split into
// g_khi/klo ; z=2 -> split into g_vhi/vlo. vmode=0: fp32 C output.
__global__ void __launch_bounds__(256, 1) mma_gemm2_kernel(
    const __nv_bfloat16* __restrict__ A,
    const __nv_bfloat16* __restrict__ B0, const __nv_bfloat16* __restrict__ B1,
    const __nv_bfloat16* __restrict__ B2,
    float* __restrict__ Cout, int vmode)
{
    const __nv_bfloat16* Bw = (blockIdx.z == 0) ? B0 : (blockIdx.z == 1) ? B1 : B2;

    extern __shared__ __align__(16) char dynsm[];
    const uint32_t base = smem_u32(dynsm);

    const int t    = threadIdx.x;
    const int wid  = t >> 5;
    const int lane = t & 31;
    const int wm0  = (wid & 3) * 64;
    const int wn0  = (wid >> 2) * 64;

    const size_t m0 = (size_t)blockIdx.y * 256;
    const size_t n0 = (size_t)blockIdx.x * 128;
    const __nv_bfloat16* Ab = A  + m0 * K3;
    const __nv_bfloat16* Bb = Bw + n0 * K3;

    const int lrow = t >> 3;
    const int lseg = (t & 7) * 8;

    float acc[4][8][4];
#pragma unroll
    for (int i = 0; i < 4; i++)
#pragma unroll
        for (int j = 0; j < 8; j++)
#pragma unroll
            for (int r = 0; r < 4; r++) acc[i][j][r] = 0.f;

    const int atile = lane >> 3;
    const int arow8 = (atile & 1) * 8;
    const int akof  = (atile >> 1) * 8;
    const int bnof  = (atile >> 1) * 8;
    const int bkof  = (atile & 1) * 8;
    const int l8    = lane & 7;

    auto issue = [&](int chunk, int stage) {
        const int seg = chunk >> 5;
        const int kin = (chunk & 31) << 6;
        const int kA  = ((seg == 2) ? 2048 : 0) + kin;
        const int kB  = ((seg == 1) ? 2048 : 0) + kin;
        const uint32_t aS = base + stage * A_STAGE;
        const uint32_t bS = base + B_OFF + stage * B_STAGE;
#pragma unroll
        for (int u = 0; u < 8; ++u) {
            int row = lrow + 32 * u;
            cp16(aS + (row * SAW + lseg) * 2, Ab + (size_t)row * K3 + kA + lseg);
        }
#pragma unroll
        for (int u = 0; u < 4; ++u) {
            int row = lrow + 32 * u;
            cp16(bS + (row * SAW + lseg) * 2, Bb + (size_t)row * K3 + kB + lseg);
        }
    };

    const int NC = 96;
    issue(0, 0);
    asm volatile("cp.async.commit_group;" ::: "memory");
    issue(1, 1);
    asm volatile("cp.async.commit_group;" ::: "memory");

    for (int c = 0; c < NC; ++c) {
        asm volatile("cp.async.wait_group 1;" ::: "memory");
        __syncthreads();
        if (c + 2 < NC) issue(c + 2, (c + 2) % 3);
        asm volatile("cp.async.commit_group;" ::: "memory");

        const uint32_t aS = base + (c % 3) * A_STAGE;
        const uint32_t bS = base + B_OFF + (c % 3) * B_STAGE;
#pragma unroll
        for (int kk = 0; kk < 64; kk += 16) {
            uint32_t af[4][4], bf[8][2];
#pragma unroll
            for (int i = 0; i < 4; ++i) {
                int row = wm0 + 16 * i + arow8 + l8;
                ldm_x4(aS + (uint32_t)(row * SAW + kk + akof) * 2,
                       af[i][0], af[i][1], af[i][2], af[i][3]);
            }
#pragma unroll
            for (int j = 0; j < 4; ++j) {
                int n = wn0 + 16 * j + bnof + l8;
                uint32_t r0, r1, r2, r3;
                ldm_x4(bS + (uint32_t)(n * SAW + kk + bkof) * 2, r0, r1, r2, r3);
                bf[2 * j + 0][0] = r0; bf[2 * j + 0][1] = r1;
                bf[2 * j + 1][0] = r2; bf[2 * j + 1][1] = r3;
            }
#pragma unroll
            for (int i = 0; i < 4; ++i)
#pragma unroll
                for (int j = 0; j < 8; ++j)
                    mma_bf16(acc[i][j], af[i], bf[j]);
        }
    }

    const int rbase = lane >> 2;
    const int cbase = (lane & 3) * 2;

    if (vmode) {
        __nv_bfloat16* dh = (blockIdx.z == 0) ? g_qhi : (blockIdx.z == 1) ? g_khi : g_vhi;
        __nv_bfloat16* dl = (blockIdx.z == 0) ? g_qlo : (blockIdx.z == 1) ? g_klo : g_vlo;
        const bool dorope = (blockIdx.z < 2);
#pragma unroll
        for (int i = 0; i < 4; ++i) {
#pragma unroll
            for (int j = 0; j < 8; ++j) {
                size_t row = m0 + wm0 + 16 * i + rbase;
                size_t col = n0 + wn0 + 8 * j + cbase;
                const int p = ((int)col & (HD - 1)) >> 1;   // RoPE pair idx in head
#pragma unroll
                for (int hrow = 0; hrow < 2; ++hrow) {
                    size_t rr = row + hrow * 8;
                    float v0 = acc[i][j][hrow * 2 + 0];
                    float v1 = acc[i][j][hrow * 2 + 1];
                    if (dorope) {
                        const int s = (int)(rr & (SEQ - 1));
                        float cc = g_cos[s * (HD / 2) + p];
                        float ss = g_sin[s * (HD / 2) + p];
                        float nx = v0 * cc - v1 * ss;
                        float ny = v0 * ss + v1 * cc;
                        v0 = nx; v1 = ny;
                    }
                    __nv_bfloat162 h2, l2;
                    h2.x = __float2bfloat16(v0);
                    l2.x = __float2bfloat16(v0 - __bfloat162float(h2.x));
                    h2.y = __float2bfloat16(v1);
                    l2.y = __float2bfloat16(v1 - __bfloat162float(h2.y));
                    *(__nv_bfloat162*)(dh + rr * DM + col) = h2;
                    *(__nv_bfloat162*)(dl + rr * DM + col) = l2;
                }
            }
        }
    } else {
#pragma unroll
        for (int i = 0; i < 4; ++i) {
#pragma unroll
            for (int j = 0; j < 8; ++j) {
                size_t row = m0 + wm0 + 16 * i + rbase;
                size_t col = n0 + wn0 + 8 * j + cbase;
                *(float2*)(Cout + row * DM + col)       = make_float2(acc[i][j][0], acc[i][j][1]);
                *(float2*)(Cout + (row + 8) * DM + col) = make_float2(acc[i][j][2], acc[i][j][3]);
            }
        }
    }
}

// ---------------- fused flash attention: S -> online softmax -> PV ----------
__global__ void __launch_bounds__(256, 1) flash_kernel()
{
    const int bm = 15 - (int)blockIdx.x;     // heavy tiles first
    const int z  = blockIdx.y;
    const int b  = z >> 4, h = z & 15;

    extern __shared__ __align__(16) char dynsm[];
    const uint32_t base = smem_u32(dynsm);

    const int t    = threadIdx.x;
    const int wid  = t >> 5;
    const int lane = t & 31;
    const int wr   = wid * 16;

    const size_t qrow0 = (size_t)(b * SEQ + bm * 128);
    const size_t kvcol = (size_t)h * HD;

    const int atile = lane >> 3, l8 = lane & 7;
    const int arow8 = (atile & 1) * 8, akof = (atile >> 1) * 8;
    const int bnof  = (atile >> 1) * 8, bkof = (atile & 1) * 8;

#pragma unroll
    for (int u = 0; u < 8; ++u) {
        int g = t + u * 256;
        int row = g >> 4;
        int gc  = (g & 15) * 8;
        uint32_t so = (uint32_t)(row * SF + gc) * 2;
        cp16(base + F_QHI + so, g_qhi + (qrow0 + row) * DM + kvcol + gc);
        cp16(base + F_QLO + so, g_qlo + (qrow0 + row) * DM + kvcol + gc);
    }

    auto issueKV = [&](int kt, int stage) {
        uint32_t sb = base + F_KV0 + (uint32_t)stage * F_STG;
        size_t kr0 = (size_t)(b * SEQ + kt * 64);
#pragma unroll
        for (int u = 0; u < 4; ++u) {
            int g = t + u * 256;
            int row = g >> 4;
            int gc  = (g & 15) * 8;
            size_t off  = (kr0 + row) * DM + kvcol + gc;
            uint32_t so = (uint32_t)(row * SF + gc) * 2;
            cp16(sb + F_OKHI + so, g_khi + off);
            cp16(sb + F_OKLO + so, g_klo + off);
            cp16(sb + F_OVHI + so, g_vhi + off);
            cp16(sb + F_OVLO + so, g_vlo + off);
        }
    };

    const int KT = 2 * bm + 2;
    issueKV(0, 0);
    asm volatile("cp.async.commit_group;" ::: "memory");
    issueKV(1, 1);
    asm volatile("cp.async.commit_group;" ::: "memory");

    float m0 = -1e30f, m1 = -1e30f, l0 = 0.f, l1 = 0.f;
    float acc_o[16][4];
#pragma unroll
    for (int j = 0; j < 16; ++j)
#pragma unroll
        for (int r = 0; r < 4; ++r) acc_o[j][r] = 0.f;

    for (int kt = 0; kt < KT; ++kt) {
        if (kt + 1 < KT) {
            asm volatile("cp.async.wait_group 1;" ::: "memory");
        } else {
            asm volatile("cp.async.wait_group 0;" ::: "memory");
        }
        __syncthreads();
        const uint32_t sS = base + F_KV0 + (uint32_t)(kt & 1) * F_STG;

        float s[8][4];
#pragma unroll
        for (int j = 0; j < 8; ++j)
#pragma unroll
            for (int r = 0; r < 4; ++r) s[j][r] = 0.f;

#pragma unroll
        for (int ks = 0; ks < 24; ++ks) {
            const int seg = ks >> 3;
            const int kc  = (ks & 7) * 16;
            const uint32_t qb = base + ((seg == 2) ? F_QLO : F_QHI);
            const uint32_t kb = sS + ((seg == 1) ? F_OKLO : F_OKHI);
            uint32_t af[4];
            ldm_x4(qb + (uint32_t)((wr + arow8 + l8) * SF + kc + akof) * 2,
                   af[0], af[1], af[2], af[3]);
            uint32_t bf[8][2];
#pragma unroll
            for (int j4 = 0; j4 < 4; ++j4) {
                uint32_t r0, r1, r2, r3;
                ldm_x4(kb + (uint32_t)((j4 * 16 + bnof + l8) * SF + kc + bkof) * 2,
                       r0, r1, r2, r3);
                bf[2 * j4 + 0][0] = r0; bf[2 * j4 + 0][1] = r1;
                bf[2 * j4 + 1][0] = r2; bf[2 * j4 + 1][1] = r3;
            }
#pragma unroll
            for (int j = 0; j < 8; ++j)
                mma_bf16(s[j], af, bf[j]);
        }

        const float sc = 0.088388347648318447f;
#pragma unroll
        for (int j = 0; j < 8; ++j)
#pragma unroll
            for (int r = 0; r < 4; ++r) s[j][r] *= sc;

        if (kt >= 2 * bm) {
            const int rg0 = bm * 128 + wr + (lane >> 2);
            const int cb  = kt * 64 + (lane & 3) * 2;
#pragma unroll
            for (int j = 0; j < 8; ++j) {
                int c0 = cb + j * 8, c1 = c0 + 1;
                if (c0 > rg0)     s[j][0] = -1e30f;
                if (c1 > rg0)     s[j][1] = -1e30f;
                if (c0 > rg0 + 8) s[j][2] = -1e30f;
                if (c1 > rg0 + 8) s[j][3] = -1e30f;
            }
        }

        float tm0 = -1e30f, tm1 = -1e30f;
#pragma unroll
        for (int j = 0; j < 8; ++j) {
            tm0 = fmaxf(tm0, fmaxf(s[j][0], s[j][1]));
            tm1 = fmaxf(tm1, fmaxf(s[j][2], s[j][3]));
        }
        tm0 = fmaxf(tm0, __shfl_xor_sync(0xffffffffu, tm0, 1));
        tm0 = fmaxf(tm0, __shfl_xor_sync(0xffffffffu, tm0, 2));
        tm1 = fmaxf(tm1, __shfl_xor_sync(0xffffffffu, tm1, 1));
        tm1 = fmaxf(tm1, __shfl_xor_sync(0xffffffffu, tm1, 2));

        const float mn0 = fmaxf(m0, tm0), mn1 = fmaxf(m1, tm1);
        const float f0 = __expf(m0 - mn0), f1 = __expf(m1 - mn1);
        m0 = mn0; m1 = mn1;

        uint32_t p01h[8], p23h[8], p01l[8], p23l[8];
        float rs0 = 0.f, rs1 = 0.f;
#pragma unroll
        for (int j = 0; j < 8; ++j) {
            float pa = __expf(s[j][0] - m0);
            float pb = __expf(s[j][1] - m0);
            float pc = __expf(s[j][2] - m1);
            float pd = __expf(s[j][3] - m1);
            rs0 += pa + pb; rs1 += pc + pd;
            __nv_bfloat16 ha = __float2bfloat16(pa), hb = __float2bfloat16(pb);
            __nv_bfloat16 hc = __float2bfloat16(pc), hd = __float2bfloat16(pd);
            p01h[j] = pack_bf16x2(__bfloat162float(ha), __bfloat162float(hb));
            p23h[j] = pack_bf16x2(__bfloat162float(hc), __bfloat162float(hd));
            p01l[j] = pack_bf16x2(pa - __bfloat162float(ha), pb - __bfloat162float(hb));
            p23l[j] = pack_bf16x2(pc - __bfloat162float(hc), pd - __bfloat162float(hd));
        }
        rs0 += __shfl_xor_sync(0xffffffffu, rs0, 1);
        rs0 += __shfl_xor_sync(0xffffffffu, rs0, 2);
        rs1 += __shfl_xor_sync(0xffffffffu, rs1, 1);
        rs1 += __shfl_xor_sync(0xffffffffu, rs1, 2);
        l0 = l0 * f0 + rs0;
        l1 = l1 * f1 + rs1;

#pragma unroll
        for (int j = 0; j < 16; ++j) {
            acc_o[j][0] *= f0; acc_o[j][1] *= f0;
            acc_o[j][2] *= f1; acc_o[j][3] *= f1;
        }

#pragma unroll
        for (int kk = 0; kk < 4; ++kk) {
            uint32_t ah[4] = {p01h[2 * kk], p23h[2 * kk], p01h[2 * kk + 1], p23h[2 * kk + 1]};
            uint32_t al[4] = {p01l[2 * kk], p23l[2 * kk], p01l[2 * kk + 1], p23l[2 * kk + 1]};
#pragma unroll
            for (int jn = 0; jn < 8; ++jn) {
                uint32_t srow = (uint32_t)(kk * 16 + bkof + l8);
                uint32_t scol = (uint32_t)(jn * 16 + bnof);
                uint32_t h0, h1, h2r, h3, q0, q1, q2, q3;
                ldm_x4t(sS + F_OVHI + (srow * SF + scol) * 2, h0, h1, h2r, h3);
                ldm_x4t(sS + F_OVLO + (srow * SF + scol) * 2, q0, q1, q2, q3);
                uint32_t bh0[2] = {h0, h1}, bh1[2] = {h2r, h3};
                uint32_t bl0[2] = {q0, q1}, bl1[2] = {q2, q3};
                mma_bf16(acc_o[2 * jn + 0], ah, bh0);
                mma_bf16(acc_o[2 * jn + 0], ah, bl0);
                mma_bf16(acc_o[2 * jn + 0], al, bh0);
                mma_bf16(acc_o[2 * jn + 1], ah, bh1);
                mma_bf16(acc_o[2 * jn + 1], ah, bl1);
                mma_bf16(acc_o[2 * jn + 1], al, bh1);
            }
        }

        __syncthreads();
        if (kt + 2 < KT) issueKV(kt + 2, kt & 1);
        asm volatile("cp.async.commit_group;" ::: "memory");
    }

    const float i0 = 1.0f / l0, i1 = 1.0f / l1;
    const size_t grow0 = qrow0 + wr + (lane >> 2);
    const int    cb    = (lane & 3) * 2;
#pragma unroll
    for (int j = 0; j < 16; ++j) {
        size_t gcol = kvcol + j * 8 + cb;
        {
            float v0 = acc_o[j][0] * i0, v1 = acc_o[j][1] * i0;
            __nv_bfloat162 h2, l2;
            h2.x = __float2bfloat16(v0);
            l2.x = __float2bfloat16(v0 - __bfloat162float(h2.x));
            h2.y = __float2bfloat16(v1);
            l2.y = __float2bfloat16(v1 - __bfloat162float(h2.y));
            *(__nv_bfloat162*)(g_aos + grow0 * K3 + gcol)        = h2;
            *(__nv_bfloat162*)(g_aos + grow0 * K3 + 2048 + gcol) = l2;
        }
        {
            float v0 = acc_o[j][2] * i1, v1 = acc_o[j][3] * i1;
            __nv_bfloat162 h2, l2;
            h2.x = __float2bfloat16(v0);
            l2.x = __float2bfloat16(v0 - __bfloat162float(h2.x));
            h2.y = __float2bfloat16(v1);
            l2.y = __float2bfloat16(v1 - __bfloat162float(h2.y));
            *(__nv_bfloat162*)(g_aos + (grow0 + 8) * K3 + gcol)        = h2;
            *(__nv_bfloat162*)(g_aos + (grow0 + 8) * K3 + 2048 + gcol) = l2;
        }
    }
}

// ---------------- launch ----------------------------------------------------
extern "C" void kernel_launch(void* const* d_in, const int* in_sizes, int n_in,
                              void* d_out, int out_size)
{
    const float* x  = (const float*)d_in[0];
    const float* Wq = (const float*)d_in[2];
    const float* Wk = (const float*)d_in[3];
    const float* Wv = (const float*)d_in[4];
    const float* Wo = (const float*)d_in[5];
    float* out = (float*)d_out;

    __nv_bfloat16 *pxs, *pws, *paos;
    cudaGetSymbolAddress((void**)&pxs,  g_xs);
    cudaGetSymbolAddress((void**)&pws,  g_ws);
    cudaGetSymbolAddress((void**)&paos, g_aos);

    cudaFuncSetAttribute(mma_gemm2_kernel,
                         cudaFuncAttributeMaxDynamicSharedMemorySize, GEMM2_SMEM);
    cudaFuncSetAttribute(flash_kernel,
                         cudaFuncAttributeMaxDynamicSharedMemorySize, FLASH_SMEM);

    // 6 launches/iter: ncu -s 5 -c 1 lands on the out-projection GEMM.
    rope_table_kernel<<<SEQ, HD / 2>>>();                       // 0
    split_x_kernel<<<(MTOT * DM) / 256, 256>>>(x);              // 1
    split_w_kernel<<<(4 * DM * DM) / 256, 256>>>(Wq, Wk, Wv, Wo); // 2

    // QKV with fused RoPE + bf16 split epilogue
    mma_gemm2_kernel<<<dim3(16, 16, 3), 256, GEMM2_SMEM>>>(     // 3
        pxs, pws + 0ULL * DM * K3, pws + 1ULL * DM * K3, pws + 2ULL * DM * K3,
        out /*unused*/, 1);

    flash_kernel<<<dim3(16, 32), 256, FLASH_SMEM>>>();          // 4

    mma_gemm2_kernel<<<dim3(16, 16, 1), 256, GEMM2_SMEM>>>(     // 5
        paos, pws + 3ULL * DM * K3, pws + 3ULL * DM * K3, pws + 3ULL * DM * K3,
        out, 0);
}

// round 13
// speedup vs baseline: 1.0951x; 1.0951x over previous
#include <cuda_runtime.h>
#include <cuda_bf16.h>
#include <math.h>
#include <stdint.h>

#define SEQ    2048
#define DM     2048
#define NH     16
#define HD     128
#define NB     2
#define MTOT   (NB * SEQ)          // 4096
#define K3     4096                // split width: [hi(2048) | lo(2048)]
#define SAW    72                  // gemm smem row stride (144B, ldmatrix conflict-free)
#define SF     136                 // flash smem row stride in bf16 (272B)

// gemm3 smem layout (dynamic): 3 stages x (A 128xSAW + B 128xSAW)
#define T_ST   (128 * SAW * 2)     // 18432 B (one operand, one stage)
#define STG_B  (2 * T_ST)          // 36864 B per stage (A then B)
#define GEMM3_SMEM (3 * STG_B)     // 110592 B  -> 2 CTAs/SM fit (221KB < 227KB)

// flash smem layout (dynamic): Q hi/lo resident + 2 KV stages
#define F_ROWB   (SF * 2)
#define F_QHI    0
#define F_QLO    (128 * F_ROWB)
#define F_KV0    (2 * 128 * F_ROWB)
#define F_OKHI   0
#define F_OKLO   (64 * F_ROWB)
#define F_OVHI   (2 * 64 * F_ROWB)
#define F_OVLO   (3 * 64 * F_ROWB)
#define F_STG    (4 * 64 * F_ROWB)
#define FLASH_SMEM (F_KV0 + 2 * F_STG)    // 208896 B

// ---------------- scratch (device globals: allocation-free rule) ------------
static __device__ float g_cos[SEQ * (HD / 2)];
static __device__ float g_sin[SEQ * (HD / 2)];
static __device__ __nv_bfloat16 g_xs [(size_t)MTOT * K3];   // x split (K3 layout)
static __device__ __nv_bfloat16 g_ws [4ULL * DM * K3];      // W splits (K3 layout)
static __device__ __nv_bfloat16 g_aos[(size_t)MTOT * K3];   // attn-out split (K3)
static __device__ __nv_bfloat16 g_qhi[(size_t)MTOT * DM];
static __device__ __nv_bfloat16 g_qlo[(size_t)MTOT * DM];
static __device__ __nv_bfloat16 g_khi[(size_t)MTOT * DM];
static __device__ __nv_bfloat16 g_klo[(size_t)MTOT * DM];
static __device__ __nv_bfloat16 g_vhi[(size_t)MTOT * DM];
static __device__ __nv_bfloat16 g_vlo[(size_t)MTOT * DM];

// ---------------- PTX helpers (baseline ISA only) ---------------------------
__device__ __forceinline__ uint32_t smem_u32(const void* p) {
    uint32_t a;
    asm("{ .reg .u64 t; cvta.to.shared.u64 t, %1; cvt.u32.u64 %0, t; }"
        : "=r"(a) : "l"(p));
    return a;
}

__device__ __forceinline__ void cp16(uint32_t saddr, const void* g) {
    asm volatile("cp.async.cg.shared.global [%0], [%1], 16;"
                 :: "r"(saddr), "l"(g));
}

__device__ __forceinline__ void ldm_x4(uint32_t addr, uint32_t& r0, uint32_t& r1,
                                       uint32_t& r2, uint32_t& r3) {
    asm volatile("ldmatrix.sync.aligned.m8n8.x4.shared.b16 {%0,%1,%2,%3}, [%4];"
                 : "=r"(r0), "=r"(r1), "=r"(r2), "=r"(r3) : "r"(addr));
}

__device__ __forceinline__ void ldm_x4t(uint32_t addr, uint32_t& r0, uint32_t& r1,
                                        uint32_t& r2, uint32_t& r3) {
    asm volatile("ldmatrix.sync.aligned.m8n8.x4.trans.shared.b16 {%0,%1,%2,%3}, [%4];"
                 : "=r"(r0), "=r"(r1), "=r"(r2), "=r"(r3) : "r"(addr));
}

__device__ __forceinline__ void mma_bf16(float* c, const uint32_t* a, const uint32_t* b) {
    asm volatile(
        "mma.sync.aligned.m16n8k16.row.col.f32.bf16.bf16.f32 "
        "{%0,%1,%2,%3}, {%4,%5,%6,%7}, {%8,%9}, {%0,%1,%2,%3};"
        : "+f"(c[0]), "+f"(c[1]), "+f"(c[2]), "+f"(c[3])
        : "r"(a[0]), "r"(a[1]), "r"(a[2]), "r"(a[3]), "r"(b[0]), "r"(b[1]));
}

__device__ __forceinline__ uint32_t pack_bf16x2(float a, float b) {
    __nv_bfloat162 h = __floats2bfloat162_rn(a, b);
    return *(uint32_t*)&h;
}

// ---------------- RoPE table (match jnp: fp32 angle, accurate trig) ---------
__global__ void rope_table_kernel()
{
    int s = blockIdx.x;
    int i = threadIdx.x;
    double e    = ((double)(2 * i)) / (double)HD;
    double powd = pow(10000.0, e);
    float  invf = (float)(1.0 / powd);
    float  fr   = (float)s * invf;
    double a    = (double)fr;
    g_cos[s * (HD / 2) + i] = (float)cos(a);
    g_sin[s * (HD / 2) + i] = (float)sin(a);
}

// ---------------- bf16 hi/lo split of x into K3-interleaved layout ----------
__global__ __launch_bounds__(256) void split_x_kernel(const float* __restrict__ src)
{
    int i = blockIdx.x * 256 + threadIdx.x;
    size_t r  = (size_t)(i >> 11);
    int    cc = i & 2047;
    float v = src[i];
    __nv_bfloat16 hi = __float2bfloat16(v);
    float hv = __bfloat162float(hi);
    __nv_bfloat16 lo = __float2bfloat16(v - hv);
    g_xs[r * K3 + cc]        = hi;
    g_xs[r * K3 + 2048 + cc] = lo;
}

// ---------------- split all 4 weight matrices in one launch -----------------
__global__ __launch_bounds__(256) void split_w_kernel(
    const float* __restrict__ W0, const float* __restrict__ W1,
    const float* __restrict__ W2, const float* __restrict__ W3)
{
    int i = blockIdx.x * 256 + threadIdx.x;
    int w = i >> 22;
    int j = i & ((1 << 22) - 1);
    const float* src = (w == 0) ? W0 : (w == 1) ? W1 : (w == 2) ? W2 : W3;
    float v = src[j];
    size_t r  = (size_t)(j >> 11);
    int    cc = j & 2047;
    __nv_bfloat16 hi = __float2bfloat16(v);
    float hv = __bfloat162float(hi);
    __nv_bfloat16 lo = __float2bfloat16(v - hv);
    __nv_bfloat16* dst = g_ws + (size_t)w * DM * K3;
    dst[r * K3 + cc]        = hi;
    dst[r * K3 + 2048 + cc] = lo;
}

// ---------------- bf16x3 GEMM v3: 128x128 CTA, 64x32 warp, 2 CTAs/SM --------
// C[m,n] = sum_k A[m,k] B[n,k]; 96 chunks of K=64 over 3 logical segments.
// 3-stage cp.async ring in dynamic smem. vmode=1 (QKV): z=0/1 -> RoPE + bf16
// split into q/k arrays; z=2 -> bf16 split into v arrays. vmode=0: fp32 C.
__global__ void __launch_bounds__(256, 2) mma_gemm3_kernel(
    const __nv_bfloat16* __restrict__ A,
    const __nv_bfloat16* __restrict__ B0, const __nv_bfloat16* __restrict__ B1,
    const __nv_bfloat16* __restrict__ B2,
    float* __restrict__ Cout, int vmode)
{
    const __nv_bfloat16* Bw = (blockIdx.z == 0) ? B0 : (blockIdx.z == 1) ? B1 : B2;

    extern __shared__ __align__(16) char dynsm[];
    const uint32_t base = smem_u32(dynsm);

    const int t    = threadIdx.x;
    const int wid  = t >> 5;
    const int lane = t & 31;
    const int wm0  = (wid >> 2) * 64;    // 2 m-slabs of 64
    const int wn0  = (wid & 3) * 32;     // 4 n-slabs of 32

    const size_t m0 = (size_t)blockIdx.y * 128;
    const size_t n0 = (size_t)blockIdx.x * 128;
    const __nv_bfloat16* Ab = A  + m0 * K3;
    const __nv_bfloat16* Bb = Bw + n0 * K3;

    const int lrow = t >> 3;             // 0..31
    const int lseg = (t & 7) * 8;        // 16B segment offset (elements)

    float acc[4][4][4];
#pragma unroll
    for (int i = 0; i < 4; i++)
#pragma unroll
        for (int j = 0; j < 4; j++)
#pragma unroll
            for (int r = 0; r < 4; r++) acc[i][j][r] = 0.f;

    const int atile = lane >> 3;
    const int arow8 = (atile & 1) * 8;
    const int akof  = (atile >> 1) * 8;
    const int bnof  = (atile >> 1) * 8;
    const int bkof  = (atile & 1) * 8;
    const int l8    = lane & 7;

    auto issue = [&](int chunk, int stage) {
        const int seg = chunk >> 5;
        const int kin = (chunk & 31) << 6;
        const int kA  = ((seg == 2) ? 2048 : 0) + kin;
        const int kB  = ((seg == 1) ? 2048 : 0) + kin;
        const uint32_t aS = base + stage * STG_B;
        const uint32_t bS = aS + T_ST;
#pragma unroll
        for (int u = 0; u < 4; ++u) {
            int row = lrow + 32 * u;
            cp16(aS + (row * SAW + lseg) * 2, Ab + (size_t)row * K3 + kA + lseg);
            cp16(bS + (row * SAW + lseg) * 2, Bb + (size_t)row * K3 + kB + lseg);
        }
    };

    const int NC = 96;
    issue(0, 0);
    asm volatile("cp.async.commit_group;" ::: "memory");
    issue(1, 1);
    asm volatile("cp.async.commit_group;" ::: "memory");

    for (int c = 0; c < NC; ++c) {
        asm volatile("cp.async.wait_group 1;" ::: "memory");
        __syncthreads();
        if (c + 2 < NC) issue(c + 2, (c + 2) % 3);
        asm volatile("cp.async.commit_group;" ::: "memory");

        const uint32_t aS = base + (c % 3) * STG_B;
        const uint32_t bS = aS + T_ST;
#pragma unroll
        for (int kk = 0; kk < 64; kk += 16) {
            uint32_t af[4][4], bf[4][2];
#pragma unroll
            for (int i = 0; i < 4; ++i) {
                int row = wm0 + 16 * i + arow8 + l8;
                ldm_x4(aS + (uint32_t)(row * SAW + kk + akof) * 2,
                       af[i][0], af[i][1], af[i][2], af[i][3]);
            }
#pragma unroll
            for (int j4 = 0; j4 < 2; ++j4) {
                int n = wn0 + 16 * j4 + bnof + l8;
                uint32_t r0, r1, r2, r3;
                ldm_x4(bS + (uint32_t)(n * SAW + kk + bkof) * 2, r0, r1, r2, r3);
                bf[2 * j4 + 0][0] = r0; bf[2 * j4 + 0][1] = r1;
                bf[2 * j4 + 1][0] = r2; bf[2 * j4 + 1][1] = r3;
            }
#pragma unroll
            for (int i = 0; i < 4; ++i)
#pragma unroll
                for (int j = 0; j < 4; ++j)
                    mma_bf16(acc[i][j], af[i], bf[j]);
        }
    }

    const int rbase = lane >> 2;
    const int cbase = (lane & 3) * 2;

    if (vmode) {
        __nv_bfloat16* dh = (blockIdx.z == 0) ? g_qhi : (blockIdx.z == 1) ? g_khi : g_vhi;
        __nv_bfloat16* dl = (blockIdx.z == 0) ? g_qlo : (blockIdx.z == 1) ? g_klo : g_vlo;
        const bool dorope = (blockIdx.z < 2);
#pragma unroll
        for (int i = 0; i < 4; ++i) {
#pragma unroll
            for (int j = 0; j < 4; ++j) {
                size_t row = m0 + wm0 + 16 * i + rbase;
                size_t col = n0 + wn0 + 8 * j + cbase;
                const int p = ((int)col & (HD - 1)) >> 1;
#pragma unroll
                for (int hrow = 0; hrow < 2; ++hrow) {
                    size_t rr = row + hrow * 8;
                    float v0 = acc[i][j][hrow * 2 + 0];
                    float v1 = acc[i][j][hrow * 2 + 1];
                    if (dorope) {
                        const int s = (int)(rr & (SEQ - 1));
                        float cc = g_cos[s * (HD / 2) + p];
                        float ss = g_sin[s * (HD / 2) + p];
                        float nx = v0 * cc - v1 * ss;
                        float ny = v0 * ss + v1 * cc;
                        v0 = nx; v1 = ny;
                    }
                    __nv_bfloat162 h2, l2;
                    h2.x = __float2bfloat16(v0);
                    l2.x = __float2bfloat16(v0 - __bfloat162float(h2.x));
                    h2.y = __float2bfloat16(v1);
                    l2.y = __float2bfloat16(v1 - __bfloat162float(h2.y));
                    *(__nv_bfloat162*)(dh + rr * DM + col) = h2;
                    *(__nv_bfloat162*)(dl + rr * DM + col) = l2;
                }
            }
        }
    } else {
#pragma unroll
        for (int i = 0; i < 4; ++i) {
#pragma unroll
            for (int j = 0; j < 4; ++j) {
                size_t row = m0 + wm0 + 16 * i + rbase;
                size_t col = n0 + wn0 + 8 * j + cbase;
                *(float2*)(Cout + row * DM + col)       = make_float2(acc[i][j][0], acc[i][j][1]);
                *(float2*)(Cout + (row + 8) * DM + col) = make_float2(acc[i][j][2], acc[i][j][3]);
            }
        }
    }
}

// ---------------- fused flash attention: S -> online softmax -> PV ----------
__global__ void __launch_bounds__(256, 1) flash_kernel()
{
    const int bm = 15 - (int)blockIdx.x;
    const int z  = blockIdx.y;
    const int b  = z >> 4, h = z & 15;

    extern __shared__ __align__(16) char dynsm[];
    const uint32_t base = smem_u32(dynsm);

    const int t    = threadIdx.x;
    const int wid  = t >> 5;
    const int lane = t & 31;
    const int wr   = wid * 16;

    const size_t qrow0 = (size_t)(b * SEQ + bm * 128);
    const size_t kvcol = (size_t)h * HD;

    const int atile = lane >> 3, l8 = lane & 7;
    const int arow8 = (atile & 1) * 8, akof = (atile >> 1) * 8;
    const int bnof  = (atile >> 1) * 8, bkof = (atile & 1) * 8;

#pragma unroll
    for (int u = 0; u < 8; ++u) {
        int g = t + u * 256;
        int row = g >> 4;
        int gc  = (g & 15) * 8;
        uint32_t so = (uint32_t)(row * SF + gc) * 2;
        cp16(base + F_QHI + so, g_qhi + (qrow0 + row) * DM + kvcol + gc);
        cp16(base + F_QLO + so, g_qlo + (qrow0 + row) * DM + kvcol + gc);
    }

    auto issueKV = [&](int kt, int stage) {
        uint32_t sb = base + F_KV0 + (uint32_t)stage * F_STG;
        size_t kr0 = (size_t)(b * SEQ + kt * 64);
#pragma unroll
        for (int u = 0; u < 4; ++u) {
            int g = t + u * 256;
            int row = g >> 4;
            int gc  = (g & 15) * 8;
            size_t off  = (kr0 + row) * DM + kvcol + gc;
            uint32_t so = (uint32_t)(row * SF + gc) * 2;
            cp16(sb + F_OKHI + so, g_khi + off);
            cp16(sb + F_OKLO + so, g_klo + off);
            cp16(sb + F_OVHI + so, g_vhi + off);
            cp16(sb + F_OVLO + so, g_vlo + off);
        }
    };

    const int KT = 2 * bm + 2;
    issueKV(0, 0);
    asm volatile("cp.async.commit_group;" ::: "memory");
    issueKV(1, 1);
    asm volatile("cp.async.commit_group;" ::: "memory");

    float m0 = -1e30f, m1 = -1e30f, l0 = 0.f, l1 = 0.f;
    float acc_o[16][4];
#pragma unroll
    for (int j = 0; j < 16; ++j)
#pragma unroll
        for (int r = 0; r < 4; ++r) acc_o[j][r] = 0.f;

    for (int kt = 0; kt < KT; ++kt) {
        if (kt + 1 < KT) {
            asm volatile("cp.async.wait_group 1;" ::: "memory");
        } else {
            asm volatile("cp.async.wait_group 0;" ::: "memory");
        }
        __syncthreads();
        const uint32_t sS = base + F_KV0 + (uint32_t)(kt & 1) * F_STG;

        float s[8][4];
#pragma unroll
        for (int j = 0; j < 8; ++j)
#pragma unroll
            for (int r = 0; r < 4; ++r) s[j][r] = 0.f;

#pragma unroll
        for (int ks = 0; ks < 24; ++ks) {
            const int seg = ks >> 3;
            const int kc  = (ks & 7) * 16;
            const uint32_t qb = base + ((seg == 2) ? F_QLO : F_QHI);
            const uint32_t kb = sS + ((seg == 1) ? F_OKLO : F_OKHI);
            uint32_t af[4];
            ldm_x4(qb + (uint32_t)((wr + arow8 + l8) * SF + kc + akof) * 2,
                   af[0], af[1], af[2], af[3]);
            uint32_t bf[8][2];
#pragma unroll
            for (int j4 = 0; j4 < 4; ++j4) {
                uint32_t r0, r1, r2, r3;
                ldm_x4(kb + (uint32_t)((j4 * 16 + bnof + l8) * SF + kc + bkof) * 2,
                       r0, r1, r2, r3);
                bf[2 * j4 + 0][0] = r0; bf[2 * j4 + 0][1] = r1;
                bf[2 * j4 + 1][0] = r2; bf[2 * j4 + 1][1] = r3;
            }
#pragma unroll
            for (int j = 0; j < 8; ++j)
                mma_bf16(s[j], af, bf[j]);
        }

        const float sc = 0.088388347648318447f;
#pragma unroll
        for (int j = 0; j < 8; ++j)
#pragma unroll
            for (int r = 0; r < 4; ++r) s[j][r] *= sc;

        if (kt >= 2 * bm) {
            const int rg0 = bm * 128 + wr + (lane >> 2);
            const int cb  = kt * 64 + (lane & 3) * 2;
#pragma unroll
            for (int j = 0; j < 8; ++j) {
                int c0 = cb + j * 8, c1 = c0 + 1;
                if (c0 > rg0)     s[j][0] = -1e30f;
                if (c1 > rg0)     s[j][1] = -1e30f;
                if (c0 > rg0 + 8) s[j][2] = -1e30f;
                if (c1 > rg0 + 8) s[j][3] = -1e30f;
            }
        }

        float tm0 = -1e30f, tm1 = -1e30f;
#pragma unroll
        for (int j = 0; j < 8; ++j) {
            tm0 = fmaxf(tm0, fmaxf(s[j][0], s[j][1]));
            tm1 = fmaxf(tm1, fmaxf(s[j][2], s[j][3]));
        }
        tm0 = fmaxf(tm0, __shfl_xor_sync(0xffffffffu, tm0, 1));
        tm0 = fmaxf(tm0, __shfl_xor_sync(0xffffffffu, tm0, 2));
        tm1 = fmaxf(tm1, __shfl_xor_sync(0xffffffffu, tm1, 1));
        tm1 = fmaxf(tm1, __shfl_xor_sync(0xffffffffu, tm1, 2));

        const float mn0 = fmaxf(m0, tm0), mn1 = fmaxf(m1, tm1);
        const float f0 = __expf(m0 - mn0), f1 = __expf(m1 - mn1);
        m0 = mn0; m1 = mn1;

        uint32_t p01h[8], p23h[8], p01l[8], p23l[8];
        float rs0 = 0.f, rs1 = 0.f;
#pragma unroll
        for (int j = 0; j < 8; ++j) {
            float pa = __expf(s[j][0] - m0);
            float pb = __expf(s[j][1] - m0);
            float pc = __expf(s[j][2] - m1);
            float pd = __expf(s[j][3] - m1);
            rs0 += pa + pb; rs1 += pc + pd;
            __nv_bfloat16 ha = __float2bfloat16(pa), hb = __float2bfloat16(pb);
            __nv_bfloat16 hc = __float2bfloat16(pc), hd = __float2bfloat16(pd);
            p01h[j] = pack_bf16x2(__bfloat162float(ha), __bfloat162float(hb));
            p23h[j] = pack_bf16x2(__bfloat162float(hc), __bfloat162float(hd));
            p01l[j] = pack_bf16x2(pa - __bfloat162float(ha), pb - __bfloat162float(hb));
            p23l[j] = pack_bf16x2(pc - __bfloat162float(hc), pd - __bfloat162float(hd));
        }
        rs0 += __shfl_xor_sync(0xffffffffu, rs0, 1);
        rs0 += __shfl_xor_sync(0xffffffffu, rs0, 2);
        rs1 += __shfl_xor_sync(0xffffffffu, rs1, 1);
        rs1 += __shfl_xor_sync(0xffffffffu, rs1, 2);
        l0 = l0 * f0 + rs0;
        l1 = l1 * f1 + rs1;

#pragma unroll
        for (int j = 0; j < 16; ++j) {
            acc_o[j][0] *= f0; acc_o[j][1] *= f0;
            acc_o[j][2] *= f1; acc_o[j][3] *= f1;
        }

#pragma unroll
        for (int kk = 0; kk < 4; ++kk) {
            uint32_t ah[4] = {p01h[2 * kk], p23h[2 * kk], p01h[2 * kk + 1], p23h[2 * kk + 1]};
            uint32_t al[4] = {p01l[2 * kk], p23l[2 * kk], p01l[2 * kk + 1], p23l[2 * kk + 1]};
#pragma unroll
            for (int jn = 0; jn < 8; ++jn) {
                uint32_t srow = (uint32_t)(kk * 16 + bkof + l8);
                uint32_t scol = (uint32_t)(jn * 16 + bnof);
                uint32_t h0, h1, h2r, h3, q0, q1, q2, q3;
                ldm_x4t(sS + F_OVHI + (srow * SF + scol) * 2, h0, h1, h2r, h3);
                ldm_x4t(sS + F_OVLO + (srow * SF + scol) * 2, q0, q1, q2, q3);
                uint32_t bh0[2] = {h0, h1}, bh1[2] = {h2r, h3};
                uint32_t bl0[2] = {q0, q1}, bl1[2] = {q2, q3};
                mma_bf16(acc_o[2 * jn + 0], ah, bh0);
                mma_bf16(acc_o[2 * jn + 0], ah, bl0);
                mma_bf16(acc_o[2 * jn + 0], al, bh0);
                mma_bf16(acc_o[2 * jn + 1], ah, bh1);
                mma_bf16(acc_o[2 * jn + 1], ah, bl1);
                mma_bf16(acc_o[2 * jn + 1], al, bh1);
            }
        }

        __syncthreads();
        if (kt + 2 < KT) issueKV(kt + 2, kt & 1);
        asm volatile("cp.async.commit_group;" ::: "memory");
    }

    const float i0 = 1.0f / l0, i1 = 1.0f / l1;
    const size_t grow0 = qrow0 + wr + (lane >> 2);
    const int    cb    = (lane & 3) * 2;
#pragma unroll
    for (int j = 0; j < 16; ++j) {
        size_t gcol = kvcol + j * 8 + cb;
        {
            float v0 = acc_o[j][0] * i0, v1 = acc_o[j][1] * i0;
            __nv_bfloat162 h2, l2;
            h2.x = __float2bfloat16(v0);
            l2.x = __float2bfloat16(v0 - __bfloat162float(h2.x));
            h2.y = __float2bfloat16(v1);
            l2.y = __float2bfloat16(v1 - __bfloat162float(h2.y));
            *(__nv_bfloat162*)(g_aos + grow0 * K3 + gcol)        = h2;
            *(__nv_bfloat162*)(g_aos + grow0 * K3 + 2048 + gcol) = l2;
        }
        {
            float v0 = acc_o[j][2] * i1, v1 = acc_o[j][3] * i1;
            __nv_bfloat162 h2, l2;
            h2.x = __float2bfloat16(v0);
            l2.x = __float2bfloat16(v0 - __bfloat162float(h2.x));
            h2.y = __float2bfloat16(v1);
            l2.y = __float2bfloat16(v1 - __bfloat162float(h2.y));
            *(__nv_bfloat162*)(g_aos + (grow0 + 8) * K3 + gcol)        = h2;
            *(__nv_bfloat162*)(g_aos + (grow0 + 8) * K3 + 2048 + gcol) = l2;
        }
    }
}

// ---------------- launch ----------------------------------------------------
extern "C" void kernel_launch(void* const* d_in, const int* in_sizes, int n_in,
                              void* d_out, int out_size)
{
    const float* x  = (const float*)d_in[0];
    const float* Wq = (const float*)d_in[2];
    const float* Wk = (const float*)d_in[3];
    const float* Wv = (const float*)d_in[4];
    const float* Wo = (const float*)d_in[5];
    float* out = (float*)d_out;

    __nv_bfloat16 *pxs, *pws, *paos;
    cudaGetSymbolAddress((void**)&pxs,  g_xs);
    cudaGetSymbolAddress((void**)&pws,  g_ws);
    cudaGetSymbolAddress((void**)&paos, g_aos);

    cudaFuncSetAttribute(mma_gemm3_kernel,
                         cudaFuncAttributeMaxDynamicSharedMemorySize, GEMM3_SMEM);
    cudaFuncSetAttribute(flash_kernel,
                         cudaFuncAttributeMaxDynamicSharedMemorySize, FLASH_SMEM);

    // 6 launches/iter: ncu -s 5 -c 1 lands on the out-projection GEMM.
    rope_table_kernel<<<SEQ, HD / 2>>>();                         // 0
    split_x_kernel<<<(MTOT * DM) / 256, 256>>>(x);                // 1
    split_w_kernel<<<(4 * DM * DM) / 256, 256>>>(Wq, Wk, Wv, Wo); // 2

    // QKV with fused RoPE + bf16 split epilogue (128x128 tiles, 2 CTAs/SM)
    mma_gemm3_kernel<<<dim3(16, 32, 3), 256, GEMM3_SMEM>>>(       // 3
        pxs, pws + 0ULL * DM * K3, pws + 1ULL * DM * K3, pws + 2ULL * DM * K3,
        out /*unused*/, 1);

    flash_kernel<<<dim3(16, 32), 256, FLASH_SMEM>>>();            // 4

    mma_gemm3_kernel<<<dim3(16, 32, 1), 256, GEMM3_SMEM>>>(       // 5
        paos, pws + 3ULL * DM * K3, pws + 3ULL * DM * K3, pws + 3ULL * DM * K3,
        out, 0);
}

// round 14
// speedup vs baseline: 1.5935x; 1.4552x over previous
#include <cuda_runtime.h>
#include <cuda_fp16.h>
#include <math.h>
#include <stdint.h>

#define SEQ    2048
#define DM     2048
#define NH     16
#define HD     128
#define NB     2
#define MTOT   (NB * SEQ)          // 4096
#define K3     4096                // B-side split width: [hi(2048) | lo(2048)]
#define SAW    72                  // gemm smem row stride (144B, ldmatrix conflict-free)
#define SF     136                 // flash smem row stride in fp16 (272B)

// gemm smem layout (dynamic): 3 stages x (A 128xSAW + B 128xSAW)
#define T_ST   (128 * SAW * 2)     // 18432 B
#define STG_B  (2 * T_ST)          // 36864 B per stage
#define GEMM3_SMEM (3 * STG_B)     // 110592 B -> 2 CTAs/SM

// flash smem layout (dynamic): Q hi resident + 2 KV stages (K hi/lo, V hi/lo)
#define F_ROWB   (SF * 2)
#define F_QHI    0
#define F_KV0    (128 * F_ROWB)            // 34816
#define F_OKHI   0
#define F_OKLO   (64 * F_ROWB)
#define F_OVHI   (2 * 64 * F_ROWB)
#define F_OVLO   (3 * 64 * F_ROWB)
#define F_STG    (4 * 64 * F_ROWB)         // 69632
#define FLASH_SMEM (F_KV0 + 2 * F_STG)     // 174080 B

// ---------------- scratch (device globals: allocation-free rule) ------------
static __device__ float g_cos[SEQ * (HD / 2)];
static __device__ float g_sin[SEQ * (HD / 2)];
static __device__ __half g_xs [(size_t)MTOT * DM];    // x fp16 (A-side: hi only)
static __device__ __half g_ws [4ULL * DM * K3];       // W fp16 hi|lo (B-side)
static __device__ __half g_aos[(size_t)MTOT * DM];    // attn-out fp16 (A-side)
static __device__ __half g_qhi[(size_t)MTOT * DM];    // roped Q (A-side)
static __device__ __half g_khi[(size_t)MTOT * DM];    // roped K hi (B-side)
static __device__ __half g_klo[(size_t)MTOT * DM];    // roped K lo
static __device__ __half g_vhi[(size_t)MTOT * DM];
static __device__ __half g_vlo[(size_t)MTOT * DM];

// ---------------- PTX helpers (baseline ISA only) ---------------------------
__device__ __forceinline__ uint32_t smem_u32(const void* p) {
    uint32_t a;
    asm("{ .reg .u64 t; cvta.to.shared.u64 t, %1; cvt.u32.u64 %0, t; }"
        : "=r"(a) : "l"(p));
    return a;
}

__device__ __forceinline__ void cp16(uint32_t saddr, const void* g) {
    asm volatile("cp.async.cg.shared.global [%0], [%1], 16;"
                 :: "r"(saddr), "l"(g));
}

__device__ __forceinline__ void ldm_x4(uint32_t addr, uint32_t& r0, uint32_t& r1,
                                       uint32_t& r2, uint32_t& r3) {
    asm volatile("ldmatrix.sync.aligned.m8n8.x4.shared.b16 {%0,%1,%2,%3}, [%4];"
                 : "=r"(r0), "=r"(r1), "=r"(r2), "=r"(r3) : "r"(addr));
}

__device__ __forceinline__ void ldm_x4t(uint32_t addr, uint32_t& r0, uint32_t& r1,
                                        uint32_t& r2, uint32_t& r3) {
    asm volatile("ldmatrix.sync.aligned.m8n8.x4.trans.shared.b16 {%0,%1,%2,%3}, [%4];"
                 : "=r"(r0), "=r"(r1), "=r"(r2), "=r"(r3) : "r"(addr));
}

__device__ __forceinline__ void mma_f16(float* c, const uint32_t* a, const uint32_t* b) {
    asm volatile(
        "mma.sync.aligned.m16n8k16.row.col.f32.f16.f16.f32 "
        "{%0,%1,%2,%3}, {%4,%5,%6,%7}, {%8,%9}, {%0,%1,%2,%3};"
        : "+f"(c[0]), "+f"(c[1]), "+f"(c[2]), "+f"(c[3])
        : "r"(a[0]), "r"(a[1]), "r"(a[2]), "r"(a[3]), "r"(b[0]), "r"(b[1]));
}

__device__ __forceinline__ uint32_t pack_h2(float a, float b) {
    __half2 h = __floats2half2_rn(a, b);
    return *(uint32_t*)&h;
}

// ---------------- RoPE table (match jnp: fp32 angle, accurate trig) ---------
__global__ void rope_table_kernel()
{
    int s = blockIdx.x;
    int i = threadIdx.x;
    double e    = ((double)(2 * i)) / (double)HD;
    double powd = pow(10000.0, e);
    float  invf = (float)(1.0 / powd);
    float  fr   = (float)s * invf;
    double a    = (double)fr;
    g_cos[s * (HD / 2) + i] = (float)cos(a);
    g_sin[s * (HD / 2) + i] = (float)sin(a);
}

// ---------------- x -> fp16 (A-side needs hi only) --------------------------
__global__ __launch_bounds__(256) void split_x_kernel(const float* __restrict__ src)
{
    int i = blockIdx.x * 256 + threadIdx.x;
    g_xs[i] = __float2half_rn(src[i]);
}

// ---------------- W -> fp16 hi/lo in [hi|lo] K3 layout ----------------------
__global__ __launch_bounds__(256) void split_w_kernel(
    const float* __restrict__ W0, const float* __restrict__ W1,
    const float* __restrict__ W2, const float* __restrict__ W3)
{
    int i = blockIdx.x * 256 + threadIdx.x;
    int w = i >> 22;
    int j = i & ((1 << 22) - 1);
    const float* src = (w == 0) ? W0 : (w == 1) ? W1 : (w == 2) ? W2 : W3;
    float v = src[j];
    size_t r  = (size_t)(j >> 11);
    int    cc = j & 2047;
    __half hi = __float2half_rn(v);
    __half lo = __float2half_rn(v - __half2float(hi));
    __half* dst = g_ws + (size_t)w * DM * K3;
    dst[r * K3 + cc]        = hi;
    dst[r * K3 + 2048 + cc] = lo;
}

// ---------------- fp16x2 GEMM: 128x128 CTA, 64x32 warp, 2 CTAs/SM -----------
// C[m,n] = sum_k A[m,k] B[n,k];  A fp16 [M x DM], B fp16 [2048 x K3] (hi|lo).
// 64 chunks of K=64: seg0 = A*Bhi, seg1 = A*Blo. 3-stage cp.async ring.
// vmode=1 (QKV): z=0 -> RoPE, Q hi; z=1 -> RoPE, K hi/lo; z=2 -> V hi/lo.
// vmode=0: fp32 C output.
__global__ void __launch_bounds__(256, 2) mma_gemm3_kernel(
    const __half* __restrict__ A,
    const __half* __restrict__ B0, const __half* __restrict__ B1,
    const __half* __restrict__ B2,
    float* __restrict__ Cout, int vmode)
{
    const __half* Bw = (blockIdx.z == 0) ? B0 : (blockIdx.z == 1) ? B1 : B2;

    extern __shared__ __align__(16) char dynsm[];
    const uint32_t base = smem_u32(dynsm);

    const int t    = threadIdx.x;
    const int wid  = t >> 5;
    const int lane = t & 31;
    const int wm0  = (wid >> 2) * 64;
    const int wn0  = (wid & 3) * 32;

    const size_t m0 = (size_t)blockIdx.y * 128;
    const size_t n0 = (size_t)blockIdx.x * 128;
    const __half* Ab = A  + m0 * DM;
    const __half* Bb = Bw + n0 * K3;

    const int lrow = t >> 3;
    const int lseg = (t & 7) * 8;

    float acc[4][4][4];
#pragma unroll
    for (int i = 0; i < 4; i++)
#pragma unroll
        for (int j = 0; j < 4; j++)
#pragma unroll
            for (int r = 0; r < 4; r++) acc[i][j][r] = 0.f;

    const int atile = lane >> 3;
    const int arow8 = (atile & 1) * 8;
    const int akof  = (atile >> 1) * 8;
    const int bnof  = (atile >> 1) * 8;
    const int bkof  = (atile & 1) * 8;
    const int l8    = lane & 7;

    auto issue = [&](int chunk, int stage) {
        const int kin = (chunk & 31) << 6;
        const int kB  = ((chunk >> 5) ? 2048 : 0) + kin;
        const uint32_t aS = base + stage * STG_B;
        const uint32_t bS = aS + T_ST;
#pragma unroll
        for (int u = 0; u < 4; ++u) {
            int row = lrow + 32 * u;
            cp16(aS + (row * SAW + lseg) * 2, Ab + (size_t)row * DM + kin + lseg);
            cp16(bS + (row * SAW + lseg) * 2, Bb + (size_t)row * K3 + kB + lseg);
        }
    };

    const int NC = 64;
    issue(0, 0);
    asm volatile("cp.async.commit_group;" ::: "memory");
    issue(1, 1);
    asm volatile("cp.async.commit_group;" ::: "memory");

    for (int c = 0; c < NC; ++c) {
        asm volatile("cp.async.wait_group 1;" ::: "memory");
        __syncthreads();
        if (c + 2 < NC) issue(c + 2, (c + 2) % 3);
        asm volatile("cp.async.commit_group;" ::: "memory");

        const uint32_t aS = base + (c % 3) * STG_B;
        const uint32_t bS = aS + T_ST;
#pragma unroll
        for (int kk = 0; kk < 64; kk += 16) {
            uint32_t af[4][4], bf[4][2];
#pragma unroll
            for (int i = 0; i < 4; ++i) {
                int row = wm0 + 16 * i + arow8 + l8;
                ldm_x4(aS + (uint32_t)(row * SAW + kk + akof) * 2,
                       af[i][0], af[i][1], af[i][2], af[i][3]);
            }
#pragma unroll
            for (int j4 = 0; j4 < 2; ++j4) {
                int n = wn0 + 16 * j4 + bnof + l8;
                uint32_t r0, r1, r2, r3;
                ldm_x4(bS + (uint32_t)(n * SAW + kk + bkof) * 2, r0, r1, r2, r3);
                bf[2 * j4 + 0][0] = r0; bf[2 * j4 + 0][1] = r1;
                bf[2 * j4 + 1][0] = r2; bf[2 * j4 + 1][1] = r3;
            }
#pragma unroll
            for (int i = 0; i < 4; ++i)
#pragma unroll
                for (int j = 0; j < 4; ++j)
                    mma_f16(acc[i][j], af[i], bf[j]);
        }
    }

    const int rbase = lane >> 2;
    const int cbase = (lane & 3) * 2;

    if (vmode) {
        const int zz = blockIdx.z;
#pragma unroll
        for (int i = 0; i < 4; ++i) {
#pragma unroll
            for (int j = 0; j < 4; ++j) {
                size_t row = m0 + wm0 + 16 * i + rbase;
                size_t col = n0 + wn0 + 8 * j + cbase;
                const int p = ((int)col & (HD - 1)) >> 1;
#pragma unroll
                for (int hrow = 0; hrow < 2; ++hrow) {
                    size_t rr = row + hrow * 8;
                    float v0 = acc[i][j][hrow * 2 + 0];
                    float v1 = acc[i][j][hrow * 2 + 1];
                    if (zz < 2) {                      // RoPE for Q and K
                        const int s = (int)(rr & (SEQ - 1));
                        float cc = g_cos[s * (HD / 2) + p];
                        float ss = g_sin[s * (HD / 2) + p];
                        float nx = v0 * cc - v1 * ss;
                        float ny = v0 * ss + v1 * cc;
                        v0 = nx; v1 = ny;
                    }
                    __half2 h2;
                    h2.x = __float2half_rn(v0);
                    h2.y = __float2half_rn(v1);
                    size_t o = rr * DM + col;
                    if (zz == 0) {
                        *(__half2*)(g_qhi + o) = h2;   // Q: hi only (A-side)
                    } else {
                        __half2 l2;
                        l2.x = __float2half_rn(v0 - __half2float(h2.x));
                        l2.y = __float2half_rn(v1 - __half2float(h2.y));
                        if (zz == 1) {
                            *(__half2*)(g_khi + o) = h2;
                            *(__half2*)(g_klo + o) = l2;
                        } else {
                            *(__half2*)(g_vhi + o) = h2;
                            *(__half2*)(g_vlo + o) = l2;
                        }
                    }
                }
            }
        }
    } else {
#pragma unroll
        for (int i = 0; i < 4; ++i) {
#pragma unroll
            for (int j = 0; j < 4; ++j) {
                size_t row = m0 + wm0 + 16 * i + rbase;
                size_t col = n0 + wn0 + 8 * j + cbase;
                *(float2*)(Cout + row * DM + col)       = make_float2(acc[i][j][0], acc[i][j][1]);
                *(float2*)(Cout + (row + 8) * DM + col) = make_float2(acc[i][j][2], acc[i][j][3]);
            }
        }
    }
}

// ---------------- fused flash attention: S -> online softmax -> PV ----------
// S = Qh*Kh + Qh*Kl ; O += Ph*Vh + Ph*Vl  (A-side lo dropped everywhere)
__global__ void __launch_bounds__(256, 1) flash_kernel()
{
    const int bm = 15 - (int)blockIdx.x;
    const int z  = blockIdx.y;
    const int b  = z >> 4, h = z & 15;

    extern __shared__ __align__(16) char dynsm[];
    const uint32_t base = smem_u32(dynsm);

    const int t    = threadIdx.x;
    const int wid  = t >> 5;
    const int lane = t & 31;
    const int wr   = wid * 16;

    const size_t qrow0 = (size_t)(b * SEQ + bm * 128);
    const size_t kvcol = (size_t)h * HD;

    const int atile = lane >> 3, l8 = lane & 7;
    const int arow8 = (atile & 1) * 8, akof = (atile >> 1) * 8;
    const int bnof  = (atile >> 1) * 8, bkof = (atile & 1) * 8;

    // Q (hi only) -> smem
#pragma unroll
    for (int u = 0; u < 8; ++u) {
        int g = t + u * 256;
        int row = g >> 4;
        int gc  = (g & 15) * 8;
        uint32_t so = (uint32_t)(row * SF + gc) * 2;
        cp16(base + F_QHI + so, g_qhi + (qrow0 + row) * DM + kvcol + gc);
    }

    auto issueKV = [&](int kt, int stage) {
        uint32_t sb = base + F_KV0 + (uint32_t)stage * F_STG;
        size_t kr0 = (size_t)(b * SEQ + kt * 64);
#pragma unroll
        for (int u = 0; u < 4; ++u) {
            int g = t + u * 256;
            int row = g >> 4;
            int gc  = (g & 15) * 8;
            size_t off  = (kr0 + row) * DM + kvcol + gc;
            uint32_t so = (uint32_t)(row * SF + gc) * 2;
            cp16(sb + F_OKHI + so, g_khi + off);
            cp16(sb + F_OKLO + so, g_klo + off);
            cp16(sb + F_OVHI + so, g_vhi + off);
            cp16(sb + F_OVLO + so, g_vlo + off);
        }
    };

    const int KT = 2 * bm + 2;
    issueKV(0, 0);
    asm volatile("cp.async.commit_group;" ::: "memory");
    issueKV(1, 1);
    asm volatile("cp.async.commit_group;" ::: "memory");

    float m0 = -1e30f, m1 = -1e30f, l0 = 0.f, l1 = 0.f;
    float acc_o[16][4];
#pragma unroll
    for (int j = 0; j < 16; ++j)
#pragma unroll
        for (int r = 0; r < 4; ++r) acc_o[j][r] = 0.f;

    for (int kt = 0; kt < KT; ++kt) {
        if (kt + 1 < KT) {
            asm volatile("cp.async.wait_group 1;" ::: "memory");
        } else {
            asm volatile("cp.async.wait_group 0;" ::: "memory");
        }
        __syncthreads();
        const uint32_t sS = base + F_KV0 + (uint32_t)(kt & 1) * F_STG;

        // ---- S = Qh.Kh^T + Qh.Kl^T (K_eff = 256) ----
        float s[8][4];
#pragma unroll
        for (int j = 0; j < 8; ++j)
#pragma unroll
            for (int r = 0; r < 4; ++r) s[j][r] = 0.f;

#pragma unroll
        for (int ks = 0; ks < 16; ++ks) {
            const int kc = (ks & 7) * 16;
            const uint32_t kb = sS + ((ks >= 8) ? F_OKLO : F_OKHI);
            uint32_t af[4];
            ldm_x4(base + F_QHI + (uint32_t)((wr + arow8 + l8) * SF + kc + akof) * 2,
                   af[0], af[1], af[2], af[3]);
            uint32_t bf[8][2];
#pragma unroll
            for (int j4 = 0; j4 < 4; ++j4) {
                uint32_t r0, r1, r2, r3;
                ldm_x4(kb + (uint32_t)((j4 * 16 + bnof + l8) * SF + kc + bkof) * 2,
                       r0, r1, r2, r3);
                bf[2 * j4 + 0][0] = r0; bf[2 * j4 + 0][1] = r1;
                bf[2 * j4 + 1][0] = r2; bf[2 * j4 + 1][1] = r3;
            }
#pragma unroll
            for (int j = 0; j < 8; ++j)
                mma_f16(s[j], af, bf[j]);
        }

        const float sc = 0.088388347648318447f;
#pragma unroll
        for (int j = 0; j < 8; ++j)
#pragma unroll
            for (int r = 0; r < 4; ++r) s[j][r] *= sc;

        if (kt >= 2 * bm) {
            const int rg0 = bm * 128 + wr + (lane >> 2);
            const int cb  = kt * 64 + (lane & 3) * 2;
#pragma unroll
            for (int j = 0; j < 8; ++j) {
                int c0 = cb + j * 8, c1 = c0 + 1;
                if (c0 > rg0)     s[j][0] = -1e30f;
                if (c1 > rg0)     s[j][1] = -1e30f;
                if (c0 > rg0 + 8) s[j][2] = -1e30f;
                if (c1 > rg0 + 8) s[j][3] = -1e30f;
            }
        }

        // ---- online softmax ----
        float tm0 = -1e30f, tm1 = -1e30f;
#pragma unroll
        for (int j = 0; j < 8; ++j) {
            tm0 = fmaxf(tm0, fmaxf(s[j][0], s[j][1]));
            tm1 = fmaxf(tm1, fmaxf(s[j][2], s[j][3]));
        }
        tm0 = fmaxf(tm0, __shfl_xor_sync(0xffffffffu, tm0, 1));
        tm0 = fmaxf(tm0, __shfl_xor_sync(0xffffffffu, tm0, 2));
        tm1 = fmaxf(tm1, __shfl_xor_sync(0xffffffffu, tm1, 1));
        tm1 = fmaxf(tm1, __shfl_xor_sync(0xffffffffu, tm1, 2));

        const float mn0 = fmaxf(m0, tm0), mn1 = fmaxf(m1, tm1);
        const float f0 = __expf(m0 - mn0), f1 = __expf(m1 - mn1);
        m0 = mn0; m1 = mn1;

        uint32_t p01h[8], p23h[8];
        float rs0 = 0.f, rs1 = 0.f;
#pragma unroll
        for (int j = 0; j < 8; ++j) {
            float pa = __expf(s[j][0] - m0);
            float pb = __expf(s[j][1] - m0);
            float pc = __expf(s[j][2] - m1);
            float pd = __expf(s[j][3] - m1);
            rs0 += pa + pb; rs1 += pc + pd;
            p01h[j] = pack_h2(pa, pb);
            p23h[j] = pack_h2(pc, pd);
        }
        rs0 += __shfl_xor_sync(0xffffffffu, rs0, 1);
        rs0 += __shfl_xor_sync(0xffffffffu, rs0, 2);
        rs1 += __shfl_xor_sync(0xffffffffu, rs1, 1);
        rs1 += __shfl_xor_sync(0xffffffffu, rs1, 2);
        l0 = l0 * f0 + rs0;
        l1 = l1 * f1 + rs1;

#pragma unroll
        for (int j = 0; j < 16; ++j) {
            acc_o[j][0] *= f0; acc_o[j][1] *= f0;
            acc_o[j][2] *= f1; acc_o[j][3] *= f1;
        }

        // ---- O += Ph.Vh + Ph.Vl ----
#pragma unroll
        for (int kk = 0; kk < 4; ++kk) {
            uint32_t ah[4] = {p01h[2 * kk], p23h[2 * kk], p01h[2 * kk + 1], p23h[2 * kk + 1]};
#pragma unroll
            for (int jn = 0; jn < 8; ++jn) {
                uint32_t srow = (uint32_t)(kk * 16 + bkof + l8);
                uint32_t scol = (uint32_t)(jn * 16 + bnof);
                uint32_t h0, h1, h2r, h3, q0, q1, q2, q3;
                ldm_x4t(sS + F_OVHI + (srow * SF + scol) * 2, h0, h1, h2r, h3);
                ldm_x4t(sS + F_OVLO + (srow * SF + scol) * 2, q0, q1, q2, q3);
                uint32_t bh0[2] = {h0, h1}, bh1[2] = {h2r, h3};
                uint32_t bl0[2] = {q0, q1}, bl1[2] = {q2, q3};
                mma_f16(acc_o[2 * jn + 0], ah, bh0);
                mma_f16(acc_o[2 * jn + 0], ah, bl0);
                mma_f16(acc_o[2 * jn + 1], ah, bh1);
                mma_f16(acc_o[2 * jn + 1], ah, bl1);
            }
        }

        __syncthreads();
        if (kt + 2 < KT) issueKV(kt + 2, kt & 1);
        asm volatile("cp.async.commit_group;" ::: "memory");
    }

    // ---- epilogue: O/l -> fp16 into g_aos (A-side: hi only) ----
    const float i0 = 1.0f / l0, i1 = 1.0f / l1;
    const size_t grow0 = qrow0 + wr + (lane >> 2);
    const int    cb    = (lane & 3) * 2;
#pragma unroll
    for (int j = 0; j < 16; ++j) {
        size_t gcol = kvcol + j * 8 + cb;
        {
            __half2 h2;
            h2.x = __float2half_rn(acc_o[j][0] * i0);
            h2.y = __float2half_rn(acc_o[j][1] * i0);
            *(__half2*)(g_aos + grow0 * DM + gcol) = h2;
        }
        {
            __half2 h2;
            h2.x = __float2half_rn(acc_o[j][2] * i1);
            h2.y = __float2half_rn(acc_o[j][3] * i1);
            *(__half2*)(g_aos + (grow0 + 8) * DM + gcol) = h2;
        }
    }
}

// ---------------- launch ----------------------------------------------------
extern "C" void kernel_launch(void* const* d_in, const int* in_sizes, int n_in,
                              void* d_out, int out_size)
{
    const float* x  = (const float*)d_in[0];
    const float* Wq = (const float*)d_in[2];
    const float* Wk = (const float*)d_in[3];
    const float* Wv = (const float*)d_in[4];
    const float* Wo = (const float*)d_in[5];
    float* out = (float*)d_out;

    __half *pxs, *pws, *paos;
    cudaGetSymbolAddress((void**)&pxs,  g_xs);
    cudaGetSymbolAddress((void**)&pws,  g_ws);
    cudaGetSymbolAddress((void**)&paos, g_aos);

    cudaFuncSetAttribute(mma_gemm3_kernel,
                         cudaFuncAttributeMaxDynamicSharedMemorySize, GEMM3_SMEM);
    cudaFuncSetAttribute(flash_kernel,
                         cudaFuncAttributeMaxDynamicSharedMemorySize, FLASH_SMEM);

    // 6 launches/iter: ncu -s 5 -c 1 lands on the out-projection GEMM.
    rope_table_kernel<<<SEQ, HD / 2>>>();                         // 0
    split_x_kernel<<<(MTOT * DM) / 256, 256>>>(x);                // 1
    split_w_kernel<<<(4 * DM * DM) / 256, 256>>>(Wq, Wk, Wv, Wo); // 2

    // QKV with fused RoPE + fp16 split epilogue
    mma_gemm3_kernel<<<dim3(16, 32, 3), 256, GEMM3_SMEM>>>(       // 3
        pxs, pws + 0ULL * DM * K3, pws + 1ULL * DM * K3, pws + 2ULL * DM * K3,
        out /*unused*/, 1);

    flash_kernel<<<dim3(16, 32), 256, FLASH_SMEM>>>();            // 4

    mma_gemm3_kernel<<<dim3(16, 32, 1), 256, GEMM3_SMEM>>>(       // 5
        paos, pws + 3ULL * DM * K3, pws + 3ULL * DM * K3, pws + 3ULL * DM * K3,
        out, 0);
}

// round 15
// speedup vs baseline: 1.6041x; 1.0066x over previous
#include <cuda_runtime.h>
#include <cuda_fp16.h>
#include <math.h>
#include <stdint.h>

#define SEQ    2048
#define DM     2048
#define NH     16
#define HD     128
#define NB     2
#define MTOT   (NB * SEQ)          // 4096
#define K3     4096                // B-side split width: [hi(2048) | lo(2048)]
#define SAW    72                  // gemm smem row stride (144B, ldmatrix conflict-free)
#define SF     136                 // flash smem row stride in fp16 (272B)

// gemm smem layout (dynamic): 3 stages x (A 128xSAW + B 128xSAW)
#define T_ST   (128 * SAW * 2)     // 18432 B
#define STG_B  (2 * T_ST)          // 36864 B per stage
#define GEMM3_SMEM (3 * STG_B)     // 110592 B -> 2 CTAs/SM

// flash smem layout (dynamic): Q hi resident + 2 KV stages (K hi/lo, V hi/lo)
#define F_ROWB   (SF * 2)
#define F_QHI    0
#define F_KV0    (128 * F_ROWB)            // 34816
#define F_OKHI   0
#define F_OKLO   (64 * F_ROWB)
#define F_OVHI   (2 * 64 * F_ROWB)
#define F_OVLO   (3 * 64 * F_ROWB)
#define F_STG    (4 * 64 * F_ROWB)         // 69632
#define FLASH_SMEM (F_KV0 + 2 * F_STG)     // 174080 B

// ---------------- scratch (device globals: allocation-free rule) ------------
static __device__ float g_cos[SEQ * (HD / 2)];
static __device__ float g_sin[SEQ * (HD / 2)];
static __device__ __half g_xs [(size_t)MTOT * DM];    // x fp16 (A-side: hi only)
static __device__ __half g_ws [4ULL * DM * K3];       // W fp16 hi|lo (B-side)
static __device__ __half g_aos[(size_t)MTOT * DM];    // attn-out fp16 (A-side)
static __device__ __half g_qhi[(size_t)MTOT * DM];    // roped Q (A-side)
static __device__ __half g_khi[(size_t)MTOT * DM];    // roped K hi (B-side)
static __device__ __half g_klo[(size_t)MTOT * DM];    // roped K lo
static __device__ __half g_vhi[(size_t)MTOT * DM];
static __device__ __half g_vlo[(size_t)MTOT * DM];

// ---------------- PTX helpers (baseline ISA only) ---------------------------
__device__ __forceinline__ uint32_t smem_u32(const void* p) {
    uint32_t a;
    asm("{ .reg .u64 t; cvta.to.shared.u64 t, %1; cvt.u32.u64 %0, t; }"
        : "=r"(a) : "l"(p));
    return a;
}

__device__ __forceinline__ void cp16(uint32_t saddr, const void* g) {
    asm volatile("cp.async.cg.shared.global [%0], [%1], 16;"
                 :: "r"(saddr), "l"(g));
}

__device__ __forceinline__ void ldm_x4(uint32_t addr, uint32_t& r0, uint32_t& r1,
                                       uint32_t& r2, uint32_t& r3) {
    asm volatile("ldmatrix.sync.aligned.m8n8.x4.shared.b16 {%0,%1,%2,%3}, [%4];"
                 : "=r"(r0), "=r"(r1), "=r"(r2), "=r"(r3) : "r"(addr));
}

__device__ __forceinline__ void ldm_x4t(uint32_t addr, uint32_t& r0, uint32_t& r1,
                                        uint32_t& r2, uint32_t& r3) {
    asm volatile("ldmatrix.sync.aligned.m8n8.x4.trans.shared.b16 {%0,%1,%2,%3}, [%4];"
                 : "=r"(r0), "=r"(r1), "=r"(r2), "=r"(r3) : "r"(addr));
}

__device__ __forceinline__ void mma_f16(float* c, const uint32_t* a, const uint32_t* b) {
    asm volatile(
        "mma.sync.aligned.m16n8k16.row.col.f32.f16.f16.f32 "
        "{%0,%1,%2,%3}, {%4,%5,%6,%7}, {%8,%9}, {%0,%1,%2,%3};"
        : "+f"(c[0]), "+f"(c[1]), "+f"(c[2]), "+f"(c[3])
        : "r"(a[0]), "r"(a[1]), "r"(a[2]), "r"(a[3]), "r"(b[0]), "r"(b[1]));
}

__device__ __forceinline__ uint32_t pack_h2(float a, float b) {
    __half2 h = __floats2half2_rn(a, b);
    return *(uint32_t*)&h;
}

// named producer/consumer barriers (ids 1..3 = stages 0..2; id 0 stays for CTA sync)
__device__ __forceinline__ void nbar_arrive(int id) {
    asm volatile("bar.arrive %0, 512;" :: "r"(id) : "memory");
}
__device__ __forceinline__ void nbar_sync(int id) {
    asm volatile("bar.sync %0, 512;" :: "r"(id) : "memory");
}

// ---------------- RoPE table (match jnp: fp32 angle, accurate trig) ---------
__global__ void rope_table_kernel()
{
    int s = blockIdx.x;
    int i = threadIdx.x;
    double e    = ((double)(2 * i)) / (double)HD;
    double powd = pow(10000.0, e);
    float  invf = (float)(1.0 / powd);
    float  fr   = (float)s * invf;
    double a    = (double)fr;
    g_cos[s * (HD / 2) + i] = (float)cos(a);
    g_sin[s * (HD / 2) + i] = (float)sin(a);
}

// ---------------- x -> fp16 (A-side needs hi only) --------------------------
__global__ __launch_bounds__(256) void split_x_kernel(const float* __restrict__ src)
{
    int i = blockIdx.x * 256 + threadIdx.x;
    g_xs[i] = __float2half_rn(src[i]);
}

// ---------------- W -> fp16 hi/lo in [hi|lo] K3 layout ----------------------
__global__ __launch_bounds__(256) void split_w_kernel(
    const float* __restrict__ W0, const float* __restrict__ W1,
    const float* __restrict__ W2, const float* __restrict__ W3)
{
    int i = blockIdx.x * 256 + threadIdx.x;
    int w = i >> 22;
    int j = i & ((1 << 22) - 1);
    const float* src = (w == 0) ? W0 : (w == 1) ? W1 : (w == 2) ? W2 : W3;
    float v = src[j];
    size_t r  = (size_t)(j >> 11);
    int    cc = j & 2047;
    __half hi = __float2half_rn(v);
    __half lo = __float2half_rn(v - __half2float(hi));
    __half* dst = g_ws + (size_t)w * DM * K3;
    dst[r * K3 + cc]        = hi;
    dst[r * K3 + 2048 + cc] = lo;
}

// ---------------- fp16x2 GEMM: 128x128 CTA, 64x32 warp, 2 CTAs/SM -----------
// C[m,n] = sum_k A[m,k] B[n,k];  A fp16 [M x DM], B fp16 [2048 x K3] (hi|lo).
// 64 chunks of K=64: seg0 = A*Bhi, seg1 = A*Blo. 3-stage cp.async ring with
// per-stage named barriers (1-chunk warp skew allowed; no full __syncthreads
// in steady state). vmode=1 (QKV): z=0 -> RoPE,Q ; z=1 -> RoPE,K hi/lo ;
// z=2 -> V hi/lo. vmode=0: fp32 C output.
__global__ void __launch_bounds__(256, 2) mma_gemm3_kernel(
    const __half* __restrict__ A,
    const __half* __restrict__ B0, const __half* __restrict__ B1,
    const __half* __restrict__ B2,
    float* __restrict__ Cout, int vmode)
{
    const __half* Bw = (blockIdx.z == 0) ? B0 : (blockIdx.z == 1) ? B1 : B2;

    extern __shared__ __align__(16) char dynsm[];
    const uint32_t base = smem_u32(dynsm);

    const int t    = threadIdx.x;
    const int wid  = t >> 5;
    const int lane = t & 31;
    const int wm0  = (wid >> 2) * 64;
    const int wn0  = (wid & 3) * 32;

    const size_t m0 = (size_t)blockIdx.y * 128;
    const size_t n0 = (size_t)blockIdx.x * 128;
    const __half* Ab = A  + m0 * DM;
    const __half* Bb = Bw + n0 * K3;

    const int lrow = t >> 3;
    const int lseg = (t & 7) * 8;

    float acc[4][4][4];
#pragma unroll
    for (int i = 0; i < 4; i++)
#pragma unroll
        for (int j = 0; j < 4; j++)
#pragma unroll
            for (int r = 0; r < 4; r++) acc[i][j][r] = 0.f;

    const int atile = lane >> 3;
    const int arow8 = (atile & 1) * 8;
    const int akof  = (atile >> 1) * 8;
    const int bnof  = (atile >> 1) * 8;
    const int bkof  = (atile & 1) * 8;
    const int l8    = lane & 7;

    auto issue = [&](int chunk, int stage) {
        const int kin = (chunk & 31) << 6;
        const int kB  = ((chunk >> 5) ? 2048 : 0) + kin;
        const uint32_t aS = base + stage * STG_B;
        const uint32_t bS = aS + T_ST;
#pragma unroll
        for (int u = 0; u < 4; ++u) {
            int row = lrow + 32 * u;
            cp16(aS + (row * SAW + lseg) * 2, Ab + (size_t)row * DM + kin + lseg);
            cp16(bS + (row * SAW + lseg) * 2, Bb + (size_t)row * K3 + kB + lseg);
        }
    };

    const int NC = 64;
    // pre-arm stage-2 barrier (its first genuine arrive would be at iter 2)
    nbar_arrive(3);
    issue(0, 0);
    asm volatile("cp.async.commit_group;" ::: "memory");
    issue(1, 1);
    asm volatile("cp.async.commit_group;" ::: "memory");
    // prologue convergence: everyone's chunk-0 copies complete before compute(0)
    asm volatile("cp.async.wait_group 1;" ::: "memory");
    __syncthreads();

    for (int c = 0; c < NC; ++c) {
        const int s2 = (c + 2) % 3;          // stage being overwritten
        nbar_sync(s2 + 1);                    // all warps done reading it (chunk c-1)
        if (c + 2 < NC) issue(c + 2, s2);
        asm volatile("cp.async.commit_group;" ::: "memory");
        asm volatile("cp.async.wait_group 1;" ::: "memory");

        const uint32_t aS = base + (c % 3) * STG_B;
        const uint32_t bS = aS + T_ST;
#pragma unroll
        for (int kk = 0; kk < 64; kk += 16) {
            uint32_t af[4][4], bf[4][2];
            // B fragments first: group-0 MMAs become ready 4 LDSMs earlier
#pragma unroll
            for (int j4 = 0; j4 < 2; ++j4) {
                int n = wn0 + 16 * j4 + bnof + l8;
                uint32_t r0, r1, r2, r3;
                ldm_x4(bS + (uint32_t)(n * SAW + kk + bkof) * 2, r0, r1, r2, r3);
                bf[2 * j4 + 0][0] = r0; bf[2 * j4 + 0][1] = r1;
                bf[2 * j4 + 1][0] = r2; bf[2 * j4 + 1][1] = r3;
            }
#pragma unroll
            for (int i = 0; i < 4; ++i) {
                int row = wm0 + 16 * i + arow8 + l8;
                ldm_x4(aS + (uint32_t)(row * SAW + kk + akof) * 2,
                       af[i][0], af[i][1], af[i][2], af[i][3]);
            }
#pragma unroll
            for (int i = 0; i < 4; ++i)
#pragma unroll
                for (int j = 0; j < 4; ++j)
                    mma_f16(acc[i][j], af[i], bf[j]);
        }
        nbar_arrive((c % 3) + 1);             // done reading stage c%3
    }

    const int rbase = lane >> 2;
    const int cbase = (lane & 3) * 2;

    if (vmode) {
        const int zz = blockIdx.z;
#pragma unroll
        for (int i = 0; i < 4; ++i) {
#pragma unroll
            for (int j = 0; j < 4; ++j) {
                size_t row = m0 + wm0 + 16 * i + rbase;
                size_t col = n0 + wn0 + 8 * j + cbase;
                const int p = ((int)col & (HD - 1)) >> 1;
#pragma unroll
                for (int hrow = 0; hrow < 2; ++hrow) {
                    size_t rr = row + hrow * 8;
                    float v0 = acc[i][j][hrow * 2 + 0];
                    float v1 = acc[i][j][hrow * 2 + 1];
                    if (zz < 2) {                      // RoPE for Q and K
                        const int s = (int)(rr & (SEQ - 1));
                        float cc = g_cos[s * (HD / 2) + p];
                        float ss = g_sin[s * (HD / 2) + p];
                        float nx = v0 * cc - v1 * ss;
                        float ny = v0 * ss + v1 * cc;
                        v0 = nx; v1 = ny;
                    }
                    __half2 h2;
                    h2.x = __float2half_rn(v0);
                    h2.y = __float2half_rn(v1);
                    size_t o = rr * DM + col;
                    if (zz == 0) {
                        *(__half2*)(g_qhi + o) = h2;   // Q: hi only (A-side)
                    } else {
                        __half2 l2;
                        l2.x = __float2half_rn(v0 - __half2float(h2.x));
                        l2.y = __float2half_rn(v1 - __half2float(h2.y));
                        if (zz == 1) {
                            *(__half2*)(g_khi + o) = h2;
                            *(__half2*)(g_klo + o) = l2;
                        } else {
                            *(__half2*)(g_vhi + o) = h2;
                            *(__half2*)(g_vlo + o) = l2;
                        }
                    }
                }
            }
        }
    } else {
#pragma unroll
        for (int i = 0; i < 4; ++i) {
#pragma unroll
            for (int j = 0; j < 4; ++j) {
                size_t row = m0 + wm0 + 16 * i + rbase;
                size_t col = n0 + wn0 + 8 * j + cbase;
                *(float2*)(Cout + row * DM + col)       = make_float2(acc[i][j][0], acc[i][j][1]);
                *(float2*)(Cout + (row + 8) * DM + col) = make_float2(acc[i][j][2], acc[i][j][3]);
            }
        }
    }
}

// ---------------- fused flash attention: S -> online softmax -> PV ----------
// S = Qh*Kh + Qh*Kl ; O += Ph*Vh + Ph*Vl  (A-side lo dropped everywhere)
__global__ void __launch_bounds__(256, 1) flash_kernel()
{
    const int bm = 15 - (int)blockIdx.x;
    const int z  = blockIdx.y;
    const int b  = z >> 4, h = z & 15;

    extern __shared__ __align__(16) char dynsm[];
    const uint32_t base = smem_u32(dynsm);

    const int t    = threadIdx.x;
    const int wid  = t >> 5;
    const int lane = t & 31;
    const int wr   = wid * 16;

    const size_t qrow0 = (size_t)(b * SEQ + bm * 128);
    const size_t kvcol = (size_t)h * HD;

    const int atile = lane >> 3, l8 = lane & 7;
    const int arow8 = (atile & 1) * 8, akof = (atile >> 1) * 8;
    const int bnof  = (atile >> 1) * 8, bkof = (atile & 1) * 8;

    // Q (hi only) -> smem
#pragma unroll
    for (int u = 0; u < 8; ++u) {
        int g = t + u * 256;
        int row = g >> 4;
        int gc  = (g & 15) * 8;
        uint32_t so = (uint32_t)(row * SF + gc) * 2;
        cp16(base + F_QHI + so, g_qhi + (qrow0 + row) * DM + kvcol + gc);
    }

    auto issueKV = [&](int kt, int stage) {
        uint32_t sb = base + F_KV0 + (uint32_t)stage * F_STG;
        size_t kr0 = (size_t)(b * SEQ + kt * 64);
#pragma unroll
        for (int u = 0; u < 4; ++u) {
            int g = t + u * 256;
            int row = g >> 4;
            int gc  = (g & 15) * 8;
            size_t off  = (kr0 + row) * DM + kvcol + gc;
            uint32_t so = (uint32_t)(row * SF + gc) * 2;
            cp16(sb + F_OKHI + so, g_khi + off);
            cp16(sb + F_OKLO + so, g_klo + off);
            cp16(sb + F_OVHI + so, g_vhi + off);
            cp16(sb + F_OVLO + so, g_vlo + off);
        }
    };

    const int KT = 2 * bm + 2;
    issueKV(0, 0);
    asm volatile("cp.async.commit_group;" ::: "memory");
    issueKV(1, 1);
    asm volatile("cp.async.commit_group;" ::: "memory");

    float m0 = -1e30f, m1 = -1e30f, l0 = 0.f, l1 = 0.f;
    float acc_o[16][4];
#pragma unroll
    for (int j = 0; j < 16; ++j)
#pragma unroll
        for (int r = 0; r < 4; ++r) acc_o[j][r] = 0.f;

    for (int kt = 0; kt < KT; ++kt) {
        if (kt + 1 < KT) {
            asm volatile("cp.async.wait_group 1;" ::: "memory");
        } else {
            asm volatile("cp.async.wait_group 0;" ::: "memory");
        }
        __syncthreads();
        const uint32_t sS = base + F_KV0 + (uint32_t)(kt & 1) * F_STG;

        // ---- S = Qh.Kh^T + Qh.Kl^T (K_eff = 256) ----
        float s[8][4];
#pragma unroll
        for (int j = 0; j < 8; ++j)
#pragma unroll
            for (int r = 0; r < 4; ++r) s[j][r] = 0.f;

#pragma unroll
        for (int ks = 0; ks < 16; ++ks) {
            const int kc = (ks & 7) * 16;
            const uint32_t kb = sS + ((ks >= 8) ? F_OKLO : F_OKHI);
            uint32_t af[4];
            ldm_x4(base + F_QHI + (uint32_t)((wr + arow8 + l8) * SF + kc + akof) * 2,
                   af[0], af[1], af[2], af[3]);
            uint32_t bf[8][2];
#pragma unroll
            for (int j4 = 0; j4 < 4; ++j4) {
                uint32_t r0, r1, r2, r3;
                ldm_x4(kb + (uint32_t)((j4 * 16 + bnof + l8) * SF + kc + bkof) * 2,
                       r0, r1, r2, r3);
                bf[2 * j4 + 0][0] = r0; bf[2 * j4 + 0][1] = r1;
                bf[2 * j4 + 1][0] = r2; bf[2 * j4 + 1][1] = r3;
            }
#pragma unroll
            for (int j = 0; j < 8; ++j)
                mma_f16(s[j], af, bf[j]);
        }

        const float sc = 0.088388347648318447f;
#pragma unroll
        for (int j = 0; j < 8; ++j)
#pragma unroll
            for (int r = 0; r < 4; ++r) s[j][r] *= sc;

        if (kt >= 2 * bm) {
            const int rg0 = bm * 128 + wr + (lane >> 2);
            const int cb  = kt * 64 + (lane & 3) * 2;
#pragma unroll
            for (int j = 0; j < 8; ++j) {
                int c0 = cb + j * 8, c1 = c0 + 1;
                if (c0 > rg0)     s[j][0] = -1e30f;
                if (c1 > rg0)     s[j][1] = -1e30f;
                if (c0 > rg0 + 8) s[j][2] = -1e30f;
                if (c1 > rg0 + 8) s[j][3] = -1e30f;
            }
        }

        // ---- online softmax ----
        float tm0 = -1e30f, tm1 = -1e30f;
#pragma unroll
        for (int j = 0; j < 8; ++j) {
            tm0 = fmaxf(tm0, fmaxf(s[j][0], s[j][1]));
            tm1 = fmaxf(tm1, fmaxf(s[j][2], s[j][3]));
        }
        tm0 = fmaxf(tm0, __shfl_xor_sync(0xffffffffu, tm0, 1));
        tm0 = fmaxf(tm0, __shfl_xor_sync(0xffffffffu, tm0, 2));
        tm1 = fmaxf(tm1, __shfl_xor_sync(0xffffffffu, tm1, 1));
        tm1 = fmaxf(tm1, __shfl_xor_sync(0xffffffffu, tm1, 2));

        const float mn0 = fmaxf(m0, tm0), mn1 = fmaxf(m1, tm1);
        const float f0 = __expf(m0 - mn0), f1 = __expf(m1 - mn1);
        m0 = mn0; m1 = mn1;

        uint32_t p01h[8], p23h[8];
        float rs0 = 0.f, rs1 = 0.f;
#pragma unroll
        for (int j = 0; j < 8; ++j) {
            float pa = __expf(s[j][0] - m0);
            float pb = __expf(s[j][1] - m0);
            float pc = __expf(s[j][2] - m1);
            float pd = __expf(s[j][3] - m1);
            rs0 += pa + pb; rs1 += pc + pd;
            p01h[j] = pack_h2(pa, pb);
            p23h[j] = pack_h2(pc, pd);
        }
        rs0 += __shfl_xor_sync(0xffffffffu, rs0, 1);
        rs0 += __shfl_xor_sync(0xffffffffu, rs0, 2);
        rs1 += __shfl_xor_sync(0xffffffffu, rs1, 1);
        rs1 += __shfl_xor_sync(0xffffffffu, rs1, 2);
        l0 = l0 * f0 + rs0;
        l1 = l1 * f1 + rs1;

#pragma unroll
        for (int j = 0; j < 16; ++j) {
            acc_o[j][0] *= f0; acc_o[j][1] *= f0;
            acc_o[j][2] *= f1; acc_o[j][3] *= f1;
        }

        // ---- O += Ph.Vh + Ph.Vl ----
#pragma unroll
        for (int kk = 0; kk < 4; ++kk) {
            uint32_t ah[4] = {p01h[2 * kk], p23h[2 * kk], p01h[2 * kk + 1], p23h[2 * kk + 1]};
#pragma unroll
            for (int jn = 0; jn < 8; ++jn) {
                uint32_t srow = (uint32_t)(kk * 16 + bkof + l8);
                uint32_t scol = (uint32_t)(jn * 16 + bnof);
                uint32_t h0, h1, h2r, h3, q0, q1, q2, q3;
                ldm_x4t(sS + F_OVHI + (srow * SF + scol) * 2, h0, h1, h2r, h3);
                ldm_x4t(sS + F_OVLO + (srow * SF + scol) * 2, q0, q1, q2, q3);
                uint32_t bh0[2] = {h0, h1}, bh1[2] = {h2r, h3};
                uint32_t bl0[2] = {q0, q1}, bl1[2] = {q2, q3};
                mma_f16(acc_o[2 * jn + 0], ah, bh0);
                mma_f16(acc_o[2 * jn + 0], ah, bl0);
                mma_f16(acc_o[2 * jn + 1], ah, bh1);
                mma_f16(acc_o[2 * jn + 1], ah, bl1);
            }
        }

        __syncthreads();
        if (kt + 2 < KT) issueKV(kt + 2, kt & 1);
        asm volatile("cp.async.commit_group;" ::: "memory");
    }

    // ---- epilogue: O/l -> fp16 into g_aos (A-side: hi only) ----
    const float i0 = 1.0f / l0, i1 = 1.0f / l1;
    const size_t grow0 = qrow0 + wr + (lane >> 2);
    const int    cb    = (lane & 3) * 2;
#pragma unroll
    for (int j = 0; j < 16; ++j) {
        size_t gcol = kvcol + j * 8 + cb;
        {
            __half2 h2;
            h2.x = __float2half_rn(acc_o[j][0] * i0);
            h2.y = __float2half_rn(acc_o[j][1] * i0);
            *(__half2*)(g_aos + grow0 * DM + gcol) = h2;
        }
        {
            __half2 h2;
            h2.x = __float2half_rn(acc_o[j][2] * i1);
            h2.y = __float2half_rn(acc_o[j][3] * i1);
            *(__half2*)(g_aos + (grow0 + 8) * DM + gcol) = h2;
        }
    }
}

// ---------------- launch ----------------------------------------------------
extern "C" void kernel_launch(void* const* d_in, const int* in_sizes, int n_in,
                              void* d_out, int out_size)
{
    const float* x  = (const float*)d_in[0];
    const float* Wq = (const float*)d_in[2];
    const float* Wk = (const float*)d_in[3];
    const float* Wv = (const float*)d_in[4];
    const float* Wo = (const float*)d_in[5];
    float* out = (float*)d_out;

    __half *pxs, *pws, *paos;
    cudaGetSymbolAddress((void**)&pxs,  g_xs);
    cudaGetSymbolAddress((void**)&pws,  g_ws);
    cudaGetSymbolAddress((void**)&paos, g_aos);

    cudaFuncSetAttribute(mma_gemm3_kernel,
                         cudaFuncAttributeMaxDynamicSharedMemorySize, GEMM3_SMEM);
    cudaFuncSetAttribute(flash_kernel,
                         cudaFuncAttributeMaxDynamicSharedMemorySize, FLASH_SMEM);

    // 6 launches/iter: ncu -s 5 -c 1 lands on the out-projection GEMM.
    rope_table_kernel<<<SEQ, HD / 2>>>();                         // 0
    split_x_kernel<<<(MTOT * DM) / 256, 256>>>(x);                // 1
    split_w_kernel<<<(4 * DM * DM) / 256, 256>>>(Wq, Wk, Wv, Wo); // 2

    // QKV with fused RoPE + fp16 split epilogue
    mma_gemm3_kernel<<<dim3(16, 32, 3), 256, GEMM3_SMEM>>>(       // 3
        pxs, pws + 0ULL * DM * K3, pws + 1ULL * DM * K3, pws + 2ULL * DM * K3,
        out /*unused*/, 1);

    flash_kernel<<<dim3(16, 32), 256, FLASH_SMEM>>>();            // 4

    mma_gemm3_kernel<<<dim3(16, 32, 1), 256, GEMM3_SMEM>>>(       // 5
        paos, pws + 3ULL * DM * K3, pws + 3ULL * DM * K3, pws + 3ULL * DM * K3,
        out, 0);
}

// round 17
// speedup vs baseline: 1.6275x; 1.0146x over previous
#include <cuda_runtime.h>
#include <cuda_fp16.h>
#include <math.h>
#include <stdint.h>

#define SEQ    2048
#define DM     2048
#define NH     16
#define HD     128
#define NB     2
#define MTOT   (NB * SEQ)          // 4096
#define K3     4096                // B-side split width: [hi(2048) | lo(2048)]
#define SAW    72                  // gemm smem row stride (144B, ldmatrix conflict-free)
#define SF     136                 // flash smem row stride in fp16 (272B)

// gemm smem layout (dynamic): 3 stages x (A 128xSAW + B 128xSAW)
#define T_ST   (128 * SAW * 2)     // 18432 B
#define STG_B  (2 * T_ST)          // 36864 B per stage
#define GEMM3_SMEM (3 * STG_B)     // 110592 B -> 2 CTAs/SM

// flash smem layout (dynamic): Q hi resident + 2 KV stages (K hi/lo, V hi/lo)
#define F_ROWB   (SF * 2)
#define F_QHI    0
#define F_KV0    (128 * F_ROWB)            // 34816
#define F_OKHI   0
#define F_OKLO   (64 * F_ROWB)
#define F_OVHI   (2 * 64 * F_ROWB)
#define F_OVLO   (3 * 64 * F_ROWB)
#define F_STG    (4 * 64 * F_ROWB)         // 69632
#define FLASH_SMEM (F_KV0 + 2 * F_STG)     // 174080 B

// ---------------- scratch (device globals: allocation-free rule) ------------
static __device__ float g_cos[SEQ * (HD / 2)];
static __device__ float g_sin[SEQ * (HD / 2)];
static __device__ __half g_xs [(size_t)MTOT * DM];    // x fp16 (A-side: hi only)
static __device__ __half g_ws [4ULL * DM * K3];       // W fp16 hi|lo (B-side)
static __device__ __half g_aos[(size_t)MTOT * DM];    // attn-out fp16 (A-side)
static __device__ __half g_qhi[(size_t)MTOT * DM];    // roped Q (A-side)
static __device__ __half g_khi[(size_t)MTOT * DM];    // roped K hi (B-side)
static __device__ __half g_klo[(size_t)MTOT * DM];    // roped K lo
static __device__ __half g_vhi[(size_t)MTOT * DM];
static __device__ __half g_vlo[(size_t)MTOT * DM];

// ---------------- PTX helpers (baseline ISA only) ---------------------------
__device__ __forceinline__ uint32_t smem_u32(const void* p) {
    uint32_t a;
    asm("{ .reg .u64 t; cvta.to.shared.u64 t, %1; cvt.u32.u64 %0, t; }"
        : "=r"(a) : "l"(p));
    return a;
}

__device__ __forceinline__ void cp16(uint32_t saddr, const void* g) {
    asm volatile("cp.async.cg.shared.global [%0], [%1], 16;"
                 :: "r"(saddr), "l"(g));
}

__device__ __forceinline__ void ldm_x4(uint32_t addr, uint32_t& r0, uint32_t& r1,
                                       uint32_t& r2, uint32_t& r3) {
    asm volatile("ldmatrix.sync.aligned.m8n8.x4.shared.b16 {%0,%1,%2,%3}, [%4];"
                 : "=r"(r0), "=r"(r1), "=r"(r2), "=r"(r3) : "r"(addr));
}

__device__ __forceinline__ void ldm_x4t(uint32_t addr, uint32_t& r0, uint32_t& r1,
                                        uint32_t& r2, uint32_t& r3) {
    asm volatile("ldmatrix.sync.aligned.m8n8.x4.trans.shared.b16 {%0,%1,%2,%3}, [%4];"
                 : "=r"(r0), "=r"(r1), "=r"(r2), "=r"(r3) : "r"(addr));
}

__device__ __forceinline__ void mma_f16(float* c, const uint32_t* a, const uint32_t* b) {
    asm volatile(
        "mma.sync.aligned.m16n8k16.row.col.f32.f16.f16.f32 "
        "{%0,%1,%2,%3}, {%4,%5,%6,%7}, {%8,%9}, {%0,%1,%2,%3};"
        : "+f"(c[0]), "+f"(c[1]), "+f"(c[2]), "+f"(c[3])
        : "r"(a[0]), "r"(a[1]), "r"(a[2]), "r"(a[3]), "r"(b[0]), "r"(b[1]));
}

__device__ __forceinline__ uint32_t pack_h2(float a, float b) {
    __half2 h = __floats2half2_rn(a, b);
    return *(uint32_t*)&h;
}

// named producer/consumer barriers (ids 1..3 = stages 0..2). Count = 256:
// 128 arrives + 128 syncs per phase (GEMM CTAs are 128 threads).
__device__ __forceinline__ void nbar_arrive(int id) {
    asm volatile("bar.arrive %0, 256;" :: "r"(id) : "memory");
}
__device__ __forceinline__ void nbar_sync(int id) {
    asm volatile("bar.sync %0, 256;" :: "r"(id) : "memory");
}

// ---------------- RoPE table (match jnp: fp32 angle, accurate trig) ---------
__global__ void rope_table_kernel()
{
    int s = blockIdx.x;
    int i = threadIdx.x;
    double e    = ((double)(2 * i)) / (double)HD;
    double powd = pow(10000.0, e);
    float  invf = (float)(1.0 / powd);
    float  fr   = (float)s * invf;
    double a    = (double)fr;
    g_cos[s * (HD / 2) + i] = (float)cos(a);
    g_sin[s * (HD / 2) + i] = (float)sin(a);
}

// ---------------- x -> fp16 (A-side needs hi only) --------------------------
__global__ __launch_bounds__(256) void split_x_kernel(const float* __restrict__ src)
{
    int i = blockIdx.x * 256 + threadIdx.x;
    g_xs[i] = __float2half_rn(src[i]);
}

// ---------------- W -> fp16 hi/lo in [hi|lo] K3 layout ----------------------
__global__ __launch_bounds__(256) void split_w_kernel(
    const float* __restrict__ W0, const float* __restrict__ W1,
    const float* __restrict__ W2, const float* __restrict__ W3)
{
    int i = blockIdx.x * 256 + threadIdx.x;
    int w = i >> 22;
    int j = i & ((1 << 22) - 1);
    const float* src = (w == 0) ? W0 : (w == 1) ? W1 : (w == 2) ? W2 : W3;
    float v = src[j];
    size_t r  = (size_t)(j >> 11);
    int    cc = j & 2047;
    __half hi = __float2half_rn(v);
    __half lo = __float2half_rn(v - __half2float(hi));
    __half* dst = g_ws + (size_t)w * DM * K3;
    dst[r * K3 + cc]        = hi;
    dst[r * K3 + 2048 + cc] = lo;
}

// ---------------- fp16x2 GEMM v4: 128x128 CTA, 4 warps of 64x64, 2 CTAs/SM --
// C[m,n] = sum_k A[m,k] B[n,k];  A fp16 [M x DM], B fp16 [2048 x K3] (hi|lo).
// 64 chunks of K=64: seg0 = A*Bhi, seg1 = A*Blo. 3-stage cp.async ring with
// per-stage named barriers. vmode=1 (QKV): z=0 RoPE,Q ; z=1 RoPE,K hi/lo ;
// z=2 V hi/lo. vmode=0: fp32 C output.
__global__ void __launch_bounds__(128, 2) mma_gemm4_kernel(
    const __half* __restrict__ A,
    const __half* __restrict__ B0, const __half* __restrict__ B1,
    const __half* __restrict__ B2,
    float* __restrict__ Cout, int vmode)
{
    const __half* Bw = (blockIdx.z == 0) ? B0 : (blockIdx.z == 1) ? B1 : B2;

    extern __shared__ __align__(16) char dynsm[];
    const uint32_t base = smem_u32(dynsm);

    const int t    = threadIdx.x;
    const int wid  = t >> 5;             // 0..3
    const int lane = t & 31;
    const int wm0  = (wid >> 1) * 64;    // 2 m-slabs of 64
    const int wn0  = (wid & 1) * 64;     // 2 n-slabs of 64

    const size_t m0 = (size_t)blockIdx.y * 128;
    const size_t n0 = (size_t)blockIdx.x * 128;
    const __half* Ab = A  + m0 * DM;
    const __half* Bb = Bw + n0 * K3;

    const int lrow = t >> 3;             // 0..15
    const int lseg = (t & 7) * 8;        // 16B segment offset (elements)

    float acc[4][8][4];
#pragma unroll
    for (int i = 0; i < 4; i++)
#pragma unroll
        for (int j = 0; j < 8; j++)
#pragma unroll
            for (int r = 0; r < 4; r++) acc[i][j][r] = 0.f;

    const int atile = lane >> 3;
    const int arow8 = (atile & 1) * 8;
    const int akof  = (atile >> 1) * 8;
    const int bnof  = (atile >> 1) * 8;
    const int bkof  = (atile & 1) * 8;
    const int l8    = lane & 7;

    auto issue = [&](int chunk, int stage) {
        const int kin = (chunk & 31) << 6;
        const int kB  = ((chunk >> 5) ? 2048 : 0) + kin;
        const uint32_t aS = base + stage * STG_B;
        const uint32_t bS = aS + T_ST;
#pragma unroll
        for (int u = 0; u < 8; ++u) {
            int row = lrow + 16 * u;
            cp16(aS + (row * SAW + lseg) * 2, Ab + (size_t)row * DM + kin + lseg);
            cp16(bS + (row * SAW + lseg) * 2, Bb + (size_t)row * K3 + kB + lseg);
        }
    };

    const int NC = 64;
    // pre-arm stage-2 barrier (first genuine arrive would be at iter 2)
    nbar_arrive(3);
    issue(0, 0);
    asm volatile("cp.async.commit_group;" ::: "memory");
    issue(1, 1);
    asm volatile("cp.async.commit_group;" ::: "memory");
    asm volatile("cp.async.wait_group 1;" ::: "memory");
    __syncthreads();

    for (int c = 0; c < NC; ++c) {
        const int s2 = (c + 2) % 3;          // stage being overwritten
        nbar_sync(s2 + 1);                    // all warps done reading it
        if (c + 2 < NC) issue(c + 2, s2);
        asm volatile("cp.async.commit_group;" ::: "memory");
        asm volatile("cp.async.wait_group 1;" ::: "memory");

        const uint32_t aS = base + (c % 3) * STG_B;
        const uint32_t bS = aS + T_ST;
#pragma unroll
        for (int kk = 0; kk < 64; kk += 16) {
            uint32_t af[4][4], bf[8][2];
            // B fragments first: group-0 MMAs ready earlier
#pragma unroll
            for (int j4 = 0; j4 < 4; ++j4) {
                int n = wn0 + 16 * j4 + bnof + l8;
                uint32_t r0, r1, r2, r3;
                ldm_x4(bS + (uint32_t)(n * SAW + kk + bkof) * 2, r0, r1, r2, r3);
                bf[2 * j4 + 0][0] = r0; bf[2 * j4 + 0][1] = r1;
                bf[2 * j4 + 1][0] = r2; bf[2 * j4 + 1][1] = r3;
            }
#pragma unroll
            for (int i = 0; i < 4; ++i) {
                int row = wm0 + 16 * i + arow8 + l8;
                ldm_x4(aS + (uint32_t)(row * SAW + kk + akof) * 2,
                       af[i][0], af[i][1], af[i][2], af[i][3]);
            }
#pragma unroll
            for (int i = 0; i < 4; ++i)
#pragma unroll
                for (int j = 0; j < 8; ++j)
                    mma_f16(acc[i][j], af[i], bf[j]);
        }
        nbar_arrive((c % 3) + 1);             // done reading stage c%3
    }

    const int rbase = lane >> 2;
    const int cbase = (lane & 3) * 2;

    if (vmode) {
        const int zz = blockIdx.z;
#pragma unroll
        for (int i = 0; i < 4; ++i) {
#pragma unroll
            for (int j = 0; j < 8; ++j) {
                size_t row = m0 + wm0 + 16 * i + rbase;
                size_t col = n0 + wn0 + 8 * j + cbase;
                const int p = ((int)col & (HD - 1)) >> 1;
#pragma unroll
                for (int hrow = 0; hrow < 2; ++hrow) {
                    size_t rr = row + hrow * 8;
                    float v0 = acc[i][j][hrow * 2 + 0];
                    float v1 = acc[i][j][hrow * 2 + 1];
                    if (zz < 2) {                      // RoPE for Q and K
                        const int s = (int)(rr & (SEQ - 1));
                        float cc = g_cos[s * (HD / 2) + p];
                        float ss = g_sin[s * (HD / 2) + p];
                        float nx = v0 * cc - v1 * ss;
                        float ny = v0 * ss + v1 * cc;
                        v0 = nx; v1 = ny;
                    }
                    __half2 h2;
                    h2.x = __float2half_rn(v0);
                    h2.y = __float2half_rn(v1);
                    size_t o = rr * DM + col;
                    if (zz == 0) {
                        *(__half2*)(g_qhi + o) = h2;   // Q: hi only (A-side)
                    } else {
                        __half2 l2;
                        l2.x = __float2half_rn(v0 - __half2float(h2.x));
                        l2.y = __float2half_rn(v1 - __half2float(h2.y));
                        if (zz == 1) {
                            *(__half2*)(g_khi + o) = h2;
                            *(__half2*)(g_klo + o) = l2;
                        } else {
                            *(__half2*)(g_vhi + o) = h2;
                            *(__half2*)(g_vlo + o) = l2;
                        }
                    }
                }
            }
        }
    } else {
#pragma unroll
        for (int i = 0; i < 4; ++i) {
#pragma unroll
            for (int j = 0; j < 8; ++j) {
                size_t row = m0 + wm0 + 16 * i + rbase;
                size_t col = n0 + wn0 + 8 * j + cbase;
                *(float2*)(Cout + row * DM + col)       = make_float2(acc[i][j][0], acc[i][j][1]);
                *(float2*)(Cout + (row + 8) * DM + col) = make_float2(acc[i][j][2], acc[i][j][3]);
            }
        }
    }
}

// ---------------- fused flash attention: S -> online softmax -> PV ----------
// S = Qh*Kh + Qh*Kl ; O += Ph*Vh + Ph*Vl  (A-side lo dropped everywhere)
__global__ void __launch_bounds__(256, 1) flash_kernel()
{
    const int bm = 15 - (int)blockIdx.x;
    const int z  = blockIdx.y;
    const int b  = z >> 4, h = z & 15;

    extern __shared__ __align__(16) char dynsm[];
    const uint32_t base = smem_u32(dynsm);

    const int t    = threadIdx.x;
    const int wid  = t >> 5;
    const int lane = t & 31;
    const int wr   = wid * 16;

    const size_t qrow0 = (size_t)(b * SEQ + bm * 128);
    const size_t kvcol = (size_t)h * HD;

    const int atile = lane >> 3, l8 = lane & 7;
    const int arow8 = (atile & 1) * 8, akof = (atile >> 1) * 8;
    const int bnof  = (atile >> 1) * 8, bkof = (atile & 1) * 8;

    // Q (hi only) -> smem
#pragma unroll
    for (int u = 0; u < 8; ++u) {
        int g = t + u * 256;
        int row = g >> 4;
        int gc  = (g & 15) * 8;
        uint32_t so = (uint32_t)(row * SF + gc) * 2;
        cp16(base + F_QHI + so, g_qhi + (qrow0 + row) * DM + kvcol + gc);
    }

    auto issueKV = [&](int kt, int stage) {
        uint32_t sb = base + F_KV0 + (uint32_t)stage * F_STG;
        size_t kr0 = (size_t)(b * SEQ + kt * 64);
#pragma unroll
        for (int u = 0; u < 4; ++u) {
            int g = t + u * 256;
            int row = g >> 4;
            int gc  = (g & 15) * 8;
            size_t off  = (kr0 + row) * DM + kvcol + gc;
            uint32_t so = (uint32_t)(row * SF + gc) * 2;
            cp16(sb + F_OKHI + so, g_khi + off);
            cp16(sb + F_OKLO + so, g_klo + off);
            cp16(sb + F_OVHI + so, g_vhi + off);
            cp16(sb + F_OVLO + so, g_vlo + off);
        }
    };

    const int KT = 2 * bm + 2;
    issueKV(0, 0);
    asm volatile("cp.async.commit_group;" ::: "memory");
    issueKV(1, 1);
    asm volatile("cp.async.commit_group;" ::: "memory");

    float m0 = -1e30f, m1 = -1e30f, l0 = 0.f, l1 = 0.f;
    float acc_o[16][4];
#pragma unroll
    for (int j = 0; j < 16; ++j)
#pragma unroll
        for (int r = 0; r < 4; ++r) acc_o[j][r] = 0.f;

    for (int kt = 0; kt < KT; ++kt) {
        if (kt + 1 < KT) {
            asm volatile("cp.async.wait_group 1;" ::: "memory");
        } else {
            asm volatile("cp.async.wait_group 0;" ::: "memory");
        }
        __syncthreads();
        const uint32_t sS = base + F_KV0 + (uint32_t)(kt & 1) * F_STG;

        // ---- S = Qh.Kh^T + Qh.Kl^T (K_eff = 256) ----
        float s[8][4];
#pragma unroll
        for (int j = 0; j < 8; ++j)
#pragma unroll
            for (int r = 0; r < 4; ++r) s[j][r] = 0.f;

#pragma unroll
        for (int ks = 0; ks < 16; ++ks) {
            const int kc = (ks & 7) * 16;
            const uint32_t kb = sS + ((ks >= 8) ? F_OKLO : F_OKHI);
            uint32_t af[4];
            ldm_x4(base + F_QHI + (uint32_t)((wr + arow8 + l8) * SF + kc + akof) * 2,
                   af[0], af[1], af[2], af[3]);
            uint32_t bf[8][2];
#pragma unroll
            for (int j4 = 0; j4 < 4; ++j4) {
                uint32_t r0, r1, r2, r3;
                ldm_x4(kb + (uint32_t)((j4 * 16 + bnof + l8) * SF + kc + bkof) * 2,
                       r0, r1, r2, r3);
                bf[2 * j4 + 0][0] = r0; bf[2 * j4 + 0][1] = r1;
                bf[2 * j4 + 1][0] = r2; bf[2 * j4 + 1][1] = r3;
            }
#pragma unroll
            for (int j = 0; j < 8; ++j)
                mma_f16(s[j], af, bf[j]);
        }

        const float sc = 0.088388347648318447f;
#pragma unroll
        for (int j = 0; j < 8; ++j)
#pragma unroll
            for (int r = 0; r < 4; ++r) s[j][r] *= sc;

        if (kt >= 2 * bm) {
            const int rg0 = bm * 128 + wr + (lane >> 2);
            const int cb  = kt * 64 + (lane & 3) * 2;
#pragma unroll
            for (int j = 0; j < 8; ++j) {
                int c0 = cb + j * 8, c1 = c0 + 1;
                if (c0 > rg0)     s[j][0] = -1e30f;
                if (c1 > rg0)     s[j][1] = -1e30f;
                if (c0 > rg0 + 8) s[j][2] = -1e30f;
                if (c1 > rg0 + 8) s[j][3] = -1e30f;
            }
        }

        // ---- online softmax ----
        float tm0 = -1e30f, tm1 = -1e30f;
#pragma unroll
        for (int j = 0; j < 8; ++j) {
            tm0 = fmaxf(tm0, fmaxf(s[j][0], s[j][1]));
            tm1 = fmaxf(tm1, fmaxf(s[j][2], s[j][3]));
        }
        tm0 = fmaxf(tm0, __shfl_xor_sync(0xffffffffu, tm0, 1));
        tm0 = fmaxf(tm0, __shfl_xor_sync(0xffffffffu, tm0, 2));
        tm1 = fmaxf(tm1, __shfl_xor_sync(0xffffffffu, tm1, 1));
        tm1 = fmaxf(tm1, __shfl_xor_sync(0xffffffffu, tm1, 2));

        const float mn0 = fmaxf(m0, tm0), mn1 = fmaxf(m1, tm1);
        const float f0 = __expf(m0 - mn0), f1 = __expf(m1 - mn1);
        m0 = mn0; m1 = mn1;

        uint32_t p01h[8], p23h[8];
        float rs0 = 0.f, rs1 = 0.f;
#pragma unroll
        for (int j = 0; j < 8; ++j) {
            float pa = __expf(s[j][0] - m0);
            float pb = __expf(s[j][1] - m0);
            float pc = __expf(s[j][2] - m1);
            float pd = __expf(s[j][3] - m1);
            rs0 += pa + pb; rs1 += pc + pd;
            p01h[j] = pack_h2(pa, pb);
            p23h[j] = pack_h2(pc, pd);
        }
        rs0 += __shfl_xor_sync(0xffffffffu, rs0, 1);
        rs0 += __shfl_xor_sync(0xffffffffu, rs0, 2);
        rs1 += __shfl_xor_sync(0xffffffffu, rs1, 1);
        rs1 += __shfl_xor_sync(0xffffffffu, rs1, 2);
        l0 = l0 * f0 + rs0;
        l1 = l1 * f1 + rs1;

#pragma unroll
        for (int j = 0; j < 16; ++j) {
            acc_o[j][0] *= f0; acc_o[j][1] *= f0;
            acc_o[j][2] *= f1; acc_o[j][3] *= f1;
        }

        // ---- O += Ph.Vh + Ph.Vl ----
#pragma unroll
        for (int kk = 0; kk < 4; ++kk) {
            uint32_t ah[4] = {p01h[2 * kk], p23h[2 * kk], p01h[2 * kk + 1], p23h[2 * kk + 1]};
#pragma unroll
            for (int jn = 0; jn < 8; ++jn) {
                uint32_t srow = (uint32_t)(kk * 16 + bkof + l8);
                uint32_t scol = (uint32_t)(jn * 16 + bnof);
                uint32_t h0, h1, h2r, h3, q0, q1, q2, q3;
                ldm_x4t(sS + F_OVHI + (srow * SF + scol) * 2, h0, h1, h2r, h3);
                ldm_x4t(sS + F_OVLO + (srow * SF + scol) * 2, q0, q1, q2, q3);
                uint32_t bh0[2] = {h0, h1}, bh1[2] = {h2r, h3};
                uint32_t bl0[2] = {q0, q1}, bl1[2] = {q2, q3};
                mma_f16(acc_o[2 * jn + 0], ah, bh0);
                mma_f16(acc_o[2 * jn + 0], ah, bl0);
                mma_f16(acc_o[2 * jn + 1], ah, bh1);
                mma_f16(acc_o[2 * jn + 1], ah, bl1);
            }
        }

        __syncthreads();
        if (kt + 2 < KT) issueKV(kt + 2, kt & 1);
        asm volatile("cp.async.commit_group;" ::: "memory");
    }

    // ---- epilogue: O/l -> fp16 into g_aos (A-side: hi only) ----
    const float i0 = 1.0f / l0, i1 = 1.0f / l1;
    const size_t grow0 = qrow0 + wr + (lane >> 2);
    const int    cb    = (lane & 3) * 2;
#pragma unroll
    for (int j = 0; j < 16; ++j) {
        size_t gcol = kvcol + j * 8 + cb;
        {
            __half2 h2;
            h2.x = __float2half_rn(acc_o[j][0] * i0);
            h2.y = __float2half_rn(acc_o[j][1] * i0);
            *(__half2*)(g_aos + grow0 * DM + gcol) = h2;
        }
        {
            __half2 h2;
            h2.x = __float2half_rn(acc_o[j][2] * i1);
            h2.y = __float2half_rn(acc_o[j][3] * i1);
            *(__half2*)(g_aos + (grow0 + 8) * DM + gcol) = h2;
        }
    }
}

// ---------------- launch ----------------------------------------------------
extern "C" void kernel_launch(void* const* d_in, const int* in_sizes, int n_in,
                              void* d_out, int out_size)
{
    const float* x  = (const float*)d_in[0];
    const float* Wq = (const float*)d_in[2];
    const float* Wk = (const float*)d_in[3];
    const float* Wv = (const float*)d_in[4];
    const float* Wo = (const float*)d_in[5];
    float* out = (float*)d_out;

    __half *pxs, *pws, *paos;
    cudaGetSymbolAddress((void**)&pxs,  g_xs);
    cudaGetSymbolAddress((void**)&pws,  g_ws);
    cudaGetSymbolAddress((void**)&paos, g_aos);

    cudaFuncSetAttribute(mma_gemm4_kernel,
                         cudaFuncAttributeMaxDynamicSharedMemorySize, GEMM3_SMEM);
    cudaFuncSetAttribute(flash_kernel,
                         cudaFuncAttributeMaxDynamicSharedMemorySize, FLASH_SMEM);

    // 6 launches/iter: ncu -s 5 -c 1 lands on the out-projection GEMM.
    rope_table_kernel<<<SEQ, HD / 2>>>();                         // 0
    split_x_kernel<<<(MTOT * DM) / 256, 256>>>(x);                // 1
    split_w_kernel<<<(4 * DM * DM) / 256, 256>>>(Wq, Wk, Wv, Wo); // 2

    // QKV with fused RoPE + fp16 split epilogue (64x64 warp tiles)
    mma_gemm4_kernel<<<dim3(16, 32, 3), 128, GEMM3_SMEM>>>(       // 3
        pxs, pws + 0ULL * DM * K3, pws + 1ULL * DM * K3, pws + 2ULL * DM * K3,
        out /*unused*/, 1);

    flash_kernel<<<dim3(16, 32), 256, FLASH_SMEM>>>();            // 4

    mma_gemm4_kernel<<<dim3(16, 32, 1), 128, GEMM3_SMEM>>>(       // 5
        paos, pws + 3ULL * DM * K3, pws + 3ULL * DM * K3, pws + 3ULL * DM * K3,
        out, 0);
}